// round 6
// baseline (speedup 1.0000x reference)
#include <cuda_runtime.h>
#include <cuda_bf16.h>
#include <math.h>
#include <stdint.h>

#define BB 2
#define SS 2048
#define DD 1024
#define HH 16
#define DH 64
#define FF 4096
#define MM (BB*SS)   // 4096 rows

// ---------------- scratch (device globals; no allocation allowed) ----------
__device__ float g_x1 [MM*DD];
__device__ float g_rel[(size_t)BB*HH*SS*SS];   // q@Er^T (upper band tiles only)
__device__ float g_x2 [MM*DD];
__device__ float g_x3 [MM*DD];

__device__ __nv_bfloat16 g_x1h[MM*DD],  g_x1l[MM*DD];
__device__ __nv_bfloat16 g_x3h[MM*DD],  g_x3l[MM*DD];
__device__ __nv_bfloat16 g_qh [MM*DD],  g_ql [MM*DD];
__device__ __nv_bfloat16 g_kh [MM*DD],  g_kl [MM*DD];
__device__ __nv_bfloat16 g_vh [MM*DD],  g_vl [MM*DD];
__device__ __nv_bfloat16 g_avh[MM*DD],  g_avl[MM*DD];
__device__ __nv_bfloat16 g_h1h[(size_t)MM*FF], g_h1l[(size_t)MM*FF];
__device__ __nv_bfloat16 g_erh[SS*DH], g_erl[SS*DH];
__device__ __nv_bfloat16 g_wqh[DD*DD], g_wql[DD*DD];
__device__ __nv_bfloat16 g_wkh[DD*DD], g_wkl[DD*DD];
__device__ __nv_bfloat16 g_wvh[DD*DD], g_wvl[DD*DD];
__device__ __nv_bfloat16 g_woh[DD*DD], g_wol[DD*DD];
__device__ __nv_bfloat16 g_w1h[(size_t)DD*FF], g_w1l[(size_t)DD*FF];
__device__ __nv_bfloat16 g_w2h[(size_t)DD*FF], g_w2l[(size_t)DD*FF];

// ======================= helpers ============================================
__device__ __forceinline__ uint32_t smem_u32(const void* p) {
    uint32_t a;
    asm("{ .reg .u64 t; cvta.to.shared.u64 t, %1; cvt.u32.u64 %0, t; }"
        : "=r"(a) : "l"(p));
    return a;
}
__device__ __forceinline__ void ldsm4(uint32_t* r, uint32_t addr) {
    asm volatile("ldmatrix.sync.aligned.m8n8.x4.shared.b16 {%0,%1,%2,%3}, [%4];"
        : "=r"(r[0]), "=r"(r[1]), "=r"(r[2]), "=r"(r[3]) : "r"(addr));
}
__device__ __forceinline__ void ldsm4t(uint32_t* r, uint32_t addr) {
    asm volatile("ldmatrix.sync.aligned.m8n8.x4.trans.shared.b16 {%0,%1,%2,%3}, [%4];"
        : "=r"(r[0]), "=r"(r[1]), "=r"(r[2]), "=r"(r[3]) : "r"(addr));
}
__device__ __forceinline__ void mma_bf16(float* c, const uint32_t* a, const uint32_t* b) {
    asm volatile("mma.sync.aligned.m16n8k16.row.col.f32.bf16.bf16.f32 "
        "{%0,%1,%2,%3}, {%4,%5,%6,%7}, {%8,%9}, {%0,%1,%2,%3};"
        : "+f"(c[0]), "+f"(c[1]), "+f"(c[2]), "+f"(c[3])
        : "r"(a[0]), "r"(a[1]), "r"(a[2]), "r"(a[3]), "r"(b[0]), "r"(b[1]));
}
__device__ __forceinline__ void cp16(uint32_t dst, const void* src) {
    asm volatile("cp.async.cg.shared.global [%0], [%1], 16;"
        :: "r"(dst), "l"(src) : "memory");
}
#define CP_COMMIT() asm volatile("cp.async.commit_group;" ::: "memory")
#define CP_WAIT1()  asm volatile("cp.async.wait_group 1;" ::: "memory")
#define CP_WAIT0()  asm volatile("cp.async.wait_group 0;" ::: "memory")

__device__ __forceinline__ void split_bf16(float v, __nv_bfloat16& h, __nv_bfloat16& l) {
    h = __float2bfloat16(v);
    l = __float2bfloat16(v - __bfloat162float(h));
}
__device__ __forceinline__ void pack_split(float x, float y, uint32_t& hi, uint32_t& lo) {
    __nv_bfloat16 xh = __float2bfloat16(x), yh = __float2bfloat16(y);
    __nv_bfloat16 xl = __float2bfloat16(x - __bfloat162float(xh));
    __nv_bfloat16 yl = __float2bfloat16(y - __bfloat162float(yh));
    __nv_bfloat162 a = __halves2bfloat162(xh, yh);
    __nv_bfloat162 b = __halves2bfloat162(xl, yl);
    hi = *(uint32_t*)&a; lo = *(uint32_t*)&b;
}

#define RSTR 144
#define ASZ (128 * RSTR)          // 18432 B per 128x64-bf16 array

// ================== weight transpose + bf16 split: [K][N]->[N][K] ===========
__global__ __launch_bounds__(256) void convBT(
    const float* __restrict__ W, __nv_bfloat16* __restrict__ Th,
    __nv_bfloat16* __restrict__ Tl, int K, int N)
{
    __shared__ float ts[32][33];
    int n0 = blockIdx.x * 32, k0 = blockIdx.y * 32;
    int tx = threadIdx.x & 31, ty = threadIdx.x >> 5;
    #pragma unroll
    for (int i = 0; i < 4; i++)
        ts[ty + 8*i][tx] = W[(size_t)(k0 + ty + 8*i) * N + n0 + tx];
    __syncthreads();
    #pragma unroll
    for (int i = 0; i < 4; i++) {
        int n = ty + 8*i;
        float v = ts[tx][n];
        __nv_bfloat16 h, l; split_bf16(v, h, l);
        size_t o = (size_t)(n0 + n) * K + k0 + tx;
        Th[o] = h; Tl[o] = l;
    }
}

// -------- elementwise bf16 split (Er) ---------------------------------------
__global__ __launch_bounds__(256) void splitE(
    const float* __restrict__ X, __nv_bfloat16* __restrict__ Xh,
    __nv_bfloat16* __restrict__ Xl, int n)
{
    int i = blockIdx.x * 1024 + threadIdx.x * 4;
    if (i >= n) return;
    float4 v = *(const float4*)(X + i);
    __nv_bfloat16 h, l;
    split_bf16(v.x, h, l); Xh[i+0] = h; Xl[i+0] = l;
    split_bf16(v.y, h, l); Xh[i+1] = h; Xl[i+1] = l;
    split_bf16(v.z, h, l); Xh[i+2] = h; Xl[i+2] = l;
    split_bf16(v.w, h, l); Xh[i+3] = h; Xl[i+3] = l;
}

// ---------------- LayerNorm: fp32 out + bf16 hi/lo split --------------------
__global__ __launch_bounds__(256) void ln_kernel(
    const float* __restrict__ X, const float* __restrict__ g,
    const float* __restrict__ be, float* __restrict__ Y,
    __nv_bfloat16* __restrict__ Yh, __nv_bfloat16* __restrict__ Yl)
{
    int row = blockIdx.x;
    size_t base = (size_t)row * DD;
    int tid = threadIdx.x;
    float4 v = *(const float4*)(X + base + tid * 4);
    float s = v.x + v.y + v.z + v.w;
    float q = v.x*v.x + v.y*v.y + v.z*v.z + v.w*v.w;

    __shared__ float rs[32], rq[32];
    #pragma unroll
    for (int o = 16; o > 0; o >>= 1) {
        s += __shfl_xor_sync(0xFFFFFFFF, s, o);
        q += __shfl_xor_sync(0xFFFFFFFF, q, o);
    }
    int lane = tid & 31, w = tid >> 5;
    if (lane == 0) { rs[w] = s; rq[w] = q; }
    __syncthreads();
    if (w == 0) {
        s = (lane < 8) ? rs[lane] : 0.f;
        q = (lane < 8) ? rq[lane] : 0.f;
        #pragma unroll
        for (int o = 4; o > 0; o >>= 1) {
            s += __shfl_xor_sync(0xFFFFFFFF, s, o);
            q += __shfl_xor_sync(0xFFFFFFFF, q, o);
        }
        if (lane == 0) { rs[0] = s; rq[0] = q; }
    }
    __syncthreads();
    float mean = rs[0] * (1.f / DD);
    float var  = rq[0] * (1.f / DD) - mean * mean;
    float rstd = rsqrtf(var + 1e-5f);

    float4 gv = *(const float4*)(g  + tid * 4);
    float4 bv = *(const float4*)(be + tid * 4);
    float4 o4;
    o4.x = (v.x - mean) * rstd * gv.x + bv.x;
    o4.y = (v.y - mean) * rstd * gv.y + bv.y;
    o4.z = (v.z - mean) * rstd * gv.z + bv.z;
    o4.w = (v.w - mean) * rstd * gv.w + bv.w;
    *(float4*)(Y + base + tid * 4) = o4;

    __nv_bfloat16 h0,l0,h1,l1,h2,l2,h3,l3;
    split_bf16(o4.x, h0, l0); split_bf16(o4.y, h1, l1);
    split_bf16(o4.z, h2, l2); split_bf16(o4.w, h3, l3);
    *(__nv_bfloat162*)(Yh + base + tid*4)     = __halves2bfloat162(h0, h1);
    *(__nv_bfloat162*)(Yh + base + tid*4 + 2) = __halves2bfloat162(h2, h3);
    *(__nv_bfloat162*)(Yl + base + tid*4)     = __halves2bfloat162(l0, l1);
    *(__nv_bfloat162*)(Yl + base + tid*4 + 2) = __halves2bfloat162(l2, l3);
}

// ====== mma.sync bf16-split GEMM, cp.async double-buffered ==================
// A (hi/lo): [M][K] bf16 row-major.  B (hi/lo): [N][K] bf16 row-major.
// smem: 2 buffers x {A_HI, A_LO, B_HI, B_LO}
#define GEMM_SMEM (8*ASZ)         // 147456 B -> 1 CTA/SM, pipelined

template<int OUTM, bool RELU, bool RES>
__global__ __launch_bounds__(256)
void gemm_mma(
    const __nv_bfloat16* __restrict__ Ah, const __nv_bfloat16* __restrict__ Al,
    const __nv_bfloat16* __restrict__ Bh, const __nv_bfloat16* __restrict__ Bl,
    const float* __restrict__ bias, const float* __restrict__ res,
    float* __restrict__ Cf, __nv_bfloat16* __restrict__ Ch,
    __nv_bfloat16* __restrict__ Cl, int N, int K, float scale)
{
    extern __shared__ char smem[];
    uint32_t sb = smem_u32(smem);
    int tid = threadIdx.x;
    int lane = tid & 31, wid = tid >> 5;
    int wm = wid & 3, wn = wid >> 2;
    int m0 = blockIdx.y * 128, n0 = blockIdx.x * 128;

    int aRow = wm * 32 + ((lane >> 3) & 1) * 8 + (lane & 7);
    uint32_t aOff = (uint32_t)aRow * RSTR + ((lane >> 4) & 1) * 16;
    int bRow = wn * 64 + ((lane >> 4) & 1) * 8 + (lane & 7);
    uint32_t bOff = (uint32_t)bRow * RSTR + ((lane >> 3) & 1) * 16;

    int ldRow = tid >> 1, ldSeg = (tid & 1) << 2;  // 128 rows x 2 threads x 4 uint4

    auto stage = [&](int c, int buf) {
        size_t koff = (size_t)c * 64;
        uint32_t bb = sb + (uint32_t)buf * (4 * ASZ);
        const uint4* pa_h = (const uint4*)(Ah + (size_t)(m0+ldRow)*K + koff);
        const uint4* pa_l = (const uint4*)(Al + (size_t)(m0+ldRow)*K + koff);
        const uint4* pb_h = (const uint4*)(Bh + (size_t)(n0+ldRow)*K + koff);
        const uint4* pb_l = (const uint4*)(Bl + (size_t)(n0+ldRow)*K + koff);
        #pragma unroll
        for (int s = 0; s < 4; s++) {
            uint32_t d = (uint32_t)ldRow * RSTR + (ldSeg + s) * 16;
            cp16(bb + 0*ASZ + d, pa_h + ldSeg + s);
            cp16(bb + 1*ASZ + d, pa_l + ldSeg + s);
            cp16(bb + 2*ASZ + d, pb_h + ldSeg + s);
            cp16(bb + 3*ASZ + d, pb_l + ldSeg + s);
        }
    };

    float acc[2][8][4] = {};

    const int chunks = K >> 6;
    stage(0, 0); CP_COMMIT();

    for (int c = 0; c < chunks; c++) {
        if (c + 1 < chunks) { stage(c + 1, (c + 1) & 1); CP_COMMIT(); CP_WAIT1(); }
        else CP_WAIT0();
        __syncthreads();

        uint32_t bb = sb + (uint32_t)(c & 1) * (4 * ASZ);
        #pragma unroll
        for (int kk = 0; kk < 4; kk++) {
            uint32_t kb = kk * 32;
            uint32_t ah[2][4], al[2][4];
            ldsm4(ah[0], bb + 0*ASZ + aOff + kb);
            ldsm4(ah[1], bb + 0*ASZ + aOff + 16*RSTR + kb);
            ldsm4(al[0], bb + 1*ASZ + aOff + kb);
            ldsm4(al[1], bb + 1*ASZ + aOff + 16*RSTR + kb);
            uint32_t bh[4][4], bl[4][4];
            #pragma unroll
            for (int jp = 0; jp < 4; jp++) {
                ldsm4(bh[jp], bb + 2*ASZ + bOff + (uint32_t)jp*16*RSTR + kb);
                ldsm4(bl[jp], bb + 3*ASZ + bOff + (uint32_t)jp*16*RSTR + kb);
            }
            #pragma unroll
            for (int im = 0; im < 2; im++)
                #pragma unroll
                for (int jn = 0; jn < 8; jn++) {
                    const uint32_t* ph = &bh[jn >> 1][(jn & 1) * 2];
                    const uint32_t* pl = &bl[jn >> 1][(jn & 1) * 2];
                    mma_bf16(acc[im][jn], ah[im], ph);
                    mma_bf16(acc[im][jn], ah[im], pl);
                    mma_bf16(acc[im][jn], al[im], ph);
                }
        }
        __syncthreads();
    }

    int r = lane >> 2, cc = (lane & 3) * 2;
    #pragma unroll
    for (int im = 0; im < 2; im++) {
        int rg0 = m0 + wm * 32 + im * 16 + r;
        #pragma unroll
        for (int jn = 0; jn < 8; jn++) {
            int col = n0 + wn * 64 + jn * 8 + cc;
            float2 bv = *(const float2*)(bias + col);
            float v0 = (acc[im][jn][0] + bv.x) * scale;
            float v1 = (acc[im][jn][1] + bv.y) * scale;
            float v2 = (acc[im][jn][2] + bv.x) * scale;
            float v3 = (acc[im][jn][3] + bv.y) * scale;
            if (RELU) {
                v0 = fmaxf(v0, 0.f); v1 = fmaxf(v1, 0.f);
                v2 = fmaxf(v2, 0.f); v3 = fmaxf(v3, 0.f);
            }
            size_t o0 = (size_t)rg0 * N + col;
            size_t o1 = (size_t)(rg0 + 8) * N + col;
            if (RES) {
                float2 r0 = *(const float2*)(res + o0);
                float2 r1 = *(const float2*)(res + o1);
                v0 += r0.x; v1 += r0.y; v2 += r1.x; v3 += r1.y;
            }
            if (OUTM == 0) {
                *(float2*)(Cf + o0) = make_float2(v0, v1);
                *(float2*)(Cf + o1) = make_float2(v2, v3);
            } else {
                __nv_bfloat16 h0,l0,h1,l1,h2,l2,h3,l3;
                split_bf16(v0, h0, l0); split_bf16(v1, h1, l1);
                split_bf16(v2, h2, l2); split_bf16(v3, h3, l3);
                *(__nv_bfloat162*)(Ch + o0) = __halves2bfloat162(h0, h1);
                *(__nv_bfloat162*)(Ch + o1) = __halves2bfloat162(h2, h3);
                *(__nv_bfloat162*)(Cl + o0) = __halves2bfloat162(l0, l1);
                *(__nv_bfloat162*)(Cl + o1) = __halves2bfloat162(l2, l3);
            }
        }
    }
}

// ========== rel = q @ Er^T, band tiles only (K = 64) ========================
#define REL_SMEM (4*ASZ)

__global__ __launch_bounds__(256)
void rel_mma(
    const __nv_bfloat16* __restrict__ Ah, const __nv_bfloat16* __restrict__ Al,
    const __nv_bfloat16* __restrict__ Bh, const __nv_bfloat16* __restrict__ Bl,
    float* __restrict__ out)
{
    int m0 = blockIdx.y * 128, n0 = blockIdx.x * 128;
    if (m0 + n0 + 255 < SS - 1) return;   // tile never read by skew gather
    int bh = blockIdx.z;
    int b = bh >> 4, h = bh & 15;

    extern __shared__ char smem[];
    uint32_t sb = smem_u32(smem);
    int tid = threadIdx.x;
    int lane = tid & 31, wid = tid >> 5;
    int wm = wid & 3, wn = wid >> 2;

    const __nv_bfloat16* Ahp = Ah + ((size_t)b * SS) * DD + h * DH;
    const __nv_bfloat16* Alp = Al + ((size_t)b * SS) * DD + h * DH;

    #pragma unroll
    for (int i = 0; i < 4; i++) {
        int u = tid + i * 256;
        int row = u >> 3, seg = u & 7;
        uint32_t d = (uint32_t)row * RSTR + seg * 16;
        cp16(sb + 0*ASZ + d, (const uint4*)(Ahp + (size_t)(m0+row)*DD) + seg);
        cp16(sb + 1*ASZ + d, (const uint4*)(Alp + (size_t)(m0+row)*DD) + seg);
        cp16(sb + 2*ASZ + d, (const uint4*)(Bh + (size_t)(n0+row)*DH) + seg);
        cp16(sb + 3*ASZ + d, (const uint4*)(Bl + (size_t)(n0+row)*DH) + seg);
    }
    CP_COMMIT(); CP_WAIT0();
    __syncthreads();

    int aRow = wm * 32 + ((lane >> 3) & 1) * 8 + (lane & 7);
    uint32_t aOff = (uint32_t)aRow * RSTR + ((lane >> 4) & 1) * 16;
    int bRow = wn * 64 + ((lane >> 4) & 1) * 8 + (lane & 7);
    uint32_t bOff = (uint32_t)bRow * RSTR + ((lane >> 3) & 1) * 16;

    float acc[2][8][4] = {};
    #pragma unroll
    for (int kk = 0; kk < 4; kk++) {
        uint32_t kb = kk * 32;
        uint32_t ah[2][4], al[2][4];
        ldsm4(ah[0], sb + 0*ASZ + aOff + kb);
        ldsm4(ah[1], sb + 0*ASZ + aOff + 16*RSTR + kb);
        ldsm4(al[0], sb + 1*ASZ + aOff + kb);
        ldsm4(al[1], sb + 1*ASZ + aOff + 16*RSTR + kb);
        uint32_t bhf[4][4], blf[4][4];
        #pragma unroll
        for (int jp = 0; jp < 4; jp++) {
            ldsm4(bhf[jp], sb + 2*ASZ + bOff + (uint32_t)jp*16*RSTR + kb);
            ldsm4(blf[jp], sb + 3*ASZ + bOff + (uint32_t)jp*16*RSTR + kb);
        }
        #pragma unroll
        for (int im = 0; im < 2; im++)
            #pragma unroll
            for (int jn = 0; jn < 8; jn++) {
                const uint32_t* ph = &bhf[jn >> 1][(jn & 1) * 2];
                const uint32_t* pl = &blf[jn >> 1][(jn & 1) * 2];
                mma_bf16(acc[im][jn], ah[im], ph);
                mma_bf16(acc[im][jn], ah[im], pl);
                mma_bf16(acc[im][jn], al[im], ph);
            }
    }

    float* ob = out + (size_t)bh * SS * SS;
    int r = lane >> 2, cc = (lane & 3) * 2;
    #pragma unroll
    for (int im = 0; im < 2; im++) {
        int rg0 = m0 + wm * 32 + im * 16 + r;
        #pragma unroll
        for (int jn = 0; jn < 8; jn++) {
            int col = n0 + wn * 64 + jn * 8 + cc;
            *(float2*)(ob + (size_t)rg0 * SS + col)      = make_float2(acc[im][jn][0], acc[im][jn][1]);
            *(float2*)(ob + (size_t)(rg0+8) * SS + col)  = make_float2(acc[im][jn][2], acc[im][jn][3]);
        }
    }
}

// ========== flash attention: softmax(qk^T + skew(rel)) @ v ==================
// CTA: one (b,h) and 128 q-rows. 8 warps x 16 rows. Chunks of 128 t-cols.
// smem: Q hi/lo persistent + 2 buffers x {K_HI, K_LO, V_HI, V_LO} (cp.async)
#define FL_SMEM (10*ASZ)    // 184320 B

__global__ __launch_bounds__(256)
void flash_mma(
    const __nv_bfloat16* __restrict__ Qh, const __nv_bfloat16* __restrict__ Ql,
    const __nv_bfloat16* __restrict__ Kh, const __nv_bfloat16* __restrict__ Kl,
    const __nv_bfloat16* __restrict__ Vh, const __nv_bfloat16* __restrict__ Vl,
    const float* __restrict__ REL,
    __nv_bfloat16* __restrict__ Oh, __nv_bfloat16* __restrict__ Ol)
{
    extern __shared__ char smem[];
    uint32_t sb = smem_u32(smem);
    int tid = threadIdx.x;
    int lane = tid & 31, w = tid >> 5;
    int s0 = blockIdx.x * 128;
    int bh = blockIdx.y;
    int b = bh >> 4, h = bh & 15;

    const __nv_bfloat16* qhb = Qh + ((size_t)b * SS) * DD + h * DH;
    const __nv_bfloat16* qlb = Ql + ((size_t)b * SS) * DD + h * DH;
    const __nv_bfloat16* khb = Kh + ((size_t)b * SS) * DD + h * DH;
    const __nv_bfloat16* klb = Kl + ((size_t)b * SS) * DD + h * DH;
    const __nv_bfloat16* vhb = Vh + ((size_t)b * SS) * DD + h * DH;
    const __nv_bfloat16* vlb = Vl + ((size_t)b * SS) * DD + h * DH;

    int ldRow = tid >> 1, ldSeg = (tid & 1) << 2;

    // stage Q (persistent) via cp.async
    {
        const uint4* pq_h = (const uint4*)(qhb + (size_t)(s0+ldRow)*DD);
        const uint4* pq_l = (const uint4*)(qlb + (size_t)(s0+ldRow)*DD);
        #pragma unroll
        for (int s = 0; s < 4; s++) {
            uint32_t d = (uint32_t)ldRow * RSTR + (ldSeg + s) * 16;
            cp16(sb + 0*ASZ + d, pq_h + ldSeg + s);
            cp16(sb + 1*ASZ + d, pq_l + ldSeg + s);
        }
    }

    auto stageKV = [&](int c, int buf) {
        size_t t0 = (size_t)c * 128;
        uint32_t bb = sb + 2*ASZ + (uint32_t)buf * (4 * ASZ);
        const uint4* pk_h = (const uint4*)(khb + (t0+ldRow)*DD);
        const uint4* pk_l = (const uint4*)(klb + (t0+ldRow)*DD);
        const uint4* pv_h = (const uint4*)(vhb + (t0+ldRow)*DD);
        const uint4* pv_l = (const uint4*)(vlb + (t0+ldRow)*DD);
        #pragma unroll
        for (int s = 0; s < 4; s++) {
            uint32_t d = (uint32_t)ldRow * RSTR + (ldSeg + s) * 16;
            cp16(bb + 0*ASZ + d, pk_h + ldSeg + s);
            cp16(bb + 1*ASZ + d, pk_l + ldSeg + s);
            cp16(bb + 2*ASZ + d, pv_h + ldSeg + s);
            cp16(bb + 3*ASZ + d, pv_l + ldSeg + s);
        }
    };

    int g = lane >> 2, qd = lane & 3;
    int sA = s0 + w * 16 + g;
    int sB = sA + 8;
    const float* rpA = REL + ((size_t)bh * SS + sA) * SS + (SS - 1 - sA);
    const float* rpB = REL + ((size_t)bh * SS + sB) * SS + (SS - 1 - sB);

    uint32_t aOff = (uint32_t)(w*16 + ((lane>>3)&1)*8 + (lane&7)) * RSTR + ((lane>>4)&1)*16;
    uint32_t bOff = (uint32_t)(((lane>>4)&1)*8 + (lane&7)) * RSTR + ((lane>>3)&1)*16;
    uint32_t vKr = ((lane>>3)&1)*8 + (lane&7);
    uint32_t vCb = ((lane>>4)&1)*16;

    float oacc[8][4] = {};
    float mA = -1e30f, mB = -1e30f, lA = 0.f, lB = 0.f;

    stageKV(0, 0); CP_COMMIT();

    for (int c = 0; c < SS/128; c++) {
        int t0 = c * 128;
        if (c + 1 < SS/128) { stageKV(c + 1, (c + 1) & 1); CP_COMMIT(); CP_WAIT1(); }
        else CP_WAIT0();
        __syncthreads();

        uint32_t bK = sb + 2*ASZ + (uint32_t)(c & 1) * (4 * ASZ);
        uint32_t bV = bK + 2*ASZ;

        // S = q @ k^T (3-term split), 16 n-tiles of 8 cols
        float sacc[16][4] = {};
        #pragma unroll
        for (int kk = 0; kk < 4; kk++) {
            uint32_t kb = kk * 32;
            uint32_t ah[4], al[4];
            ldsm4(ah, sb + 0*ASZ + aOff + kb);
            ldsm4(al, sb + 1*ASZ + aOff + kb);
            #pragma unroll
            for (int jp = 0; jp < 8; jp++) {
                uint32_t bhf[4], blf[4];
                ldsm4(bhf, bK + bOff + (uint32_t)jp*16*RSTR + kb);
                ldsm4(blf, bK + ASZ + bOff + (uint32_t)jp*16*RSTR + kb);
                #pragma unroll
                for (int e = 0; e < 2; e++) {
                    int jn = jp * 2 + e;
                    mma_bf16(sacc[jn], ah, &bhf[e*2]);
                    mma_bf16(sacc[jn], ah, &blf[e*2]);
                    mma_bf16(sacc[jn], al, &bhf[e*2]);
                }
            }
        }

        // skew add
        if (t0 <= sA) {
            #pragma unroll
            for (int jn = 0; jn < 16; jn++) {
                int t = t0 + jn * 8 + qd * 2;
                if (t     <= sA) sacc[jn][0] += __ldg(rpA + t);
                if (t + 1 <= sA) sacc[jn][1] += __ldg(rpA + t + 1);
            }
        }
        if (t0 <= sB) {
            #pragma unroll
            for (int jn = 0; jn < 16; jn++) {
                int t = t0 + jn * 8 + qd * 2;
                if (t     <= sB) sacc[jn][2] += __ldg(rpB + t);
                if (t + 1 <= sB) sacc[jn][3] += __ldg(rpB + t + 1);
            }
        }

        // online softmax
        float cmA = -1e30f, cmB = -1e30f;
        #pragma unroll
        for (int jn = 0; jn < 16; jn++) {
            cmA = fmaxf(cmA, fmaxf(sacc[jn][0], sacc[jn][1]));
            cmB = fmaxf(cmB, fmaxf(sacc[jn][2], sacc[jn][3]));
        }
        cmA = fmaxf(cmA, __shfl_xor_sync(0xFFFFFFFF, cmA, 1));
        cmA = fmaxf(cmA, __shfl_xor_sync(0xFFFFFFFF, cmA, 2));
        cmB = fmaxf(cmB, __shfl_xor_sync(0xFFFFFFFF, cmB, 1));
        cmB = fmaxf(cmB, __shfl_xor_sync(0xFFFFFFFF, cmB, 2));
        float mnA = fmaxf(mA, cmA), mnB = fmaxf(mB, cmB);
        float alA = __expf(mA - mnA), alB = __expf(mB - mnB);
        mA = mnA; mB = mnB;

        float suA = 0.f, suB = 0.f;
        #pragma unroll
        for (int jn = 0; jn < 16; jn++) {
            sacc[jn][0] = __expf(sacc[jn][0] - mnA);
            sacc[jn][1] = __expf(sacc[jn][1] - mnA);
            sacc[jn][2] = __expf(sacc[jn][2] - mnB);
            sacc[jn][3] = __expf(sacc[jn][3] - mnB);
            suA += sacc[jn][0] + sacc[jn][1];
            suB += sacc[jn][2] + sacc[jn][3];
        }
        suA += __shfl_xor_sync(0xFFFFFFFF, suA, 1);
        suA += __shfl_xor_sync(0xFFFFFFFF, suA, 2);
        suB += __shfl_xor_sync(0xFFFFFFFF, suB, 1);
        suB += __shfl_xor_sync(0xFFFFFFFF, suB, 2);
        lA = lA * alA + suA;
        lB = lB * alB + suB;

        #pragma unroll
        for (int jn = 0; jn < 8; jn++) {
            oacc[jn][0] *= alA; oacc[jn][1] *= alA;
            oacc[jn][2] *= alB; oacc[jn][3] *= alB;
        }

        // O += P @ V (3-term)
        #pragma unroll
        for (int k2 = 0; k2 < 8; k2++) {
            uint32_t pah[4], pal[4];
            pack_split(sacc[2*k2][0],   sacc[2*k2][1],   pah[0], pal[0]);
            pack_split(sacc[2*k2][2],   sacc[2*k2][3],   pah[1], pal[1]);
            pack_split(sacc[2*k2+1][0], sacc[2*k2+1][1], pah[2], pal[2]);
            pack_split(sacc[2*k2+1][2], sacc[2*k2+1][3], pah[3], pal[3]);
            uint32_t vRowOff = (uint32_t)(k2 * 16 + vKr) * RSTR;
            #pragma unroll
            for (int jp = 0; jp < 4; jp++) {
                uint32_t vh4[4], vl4[4];
                ldsm4t(vh4, bV + vRowOff + vCb + jp * 32);
                ldsm4t(vl4, bV + ASZ + vRowOff + vCb + jp * 32);
                #pragma unroll
                for (int e = 0; e < 2; e++) {
                    int jo = jp * 2 + e;
                    mma_bf16(oacc[jo], pah, &vh4[e*2]);
                    mma_bf16(oacc[jo], pah, &vl4[e*2]);
                    mma_bf16(oacc[jo], pal, &vh4[e*2]);
                }
            }
        }
        __syncthreads();
    }

    // epilogue: normalize + split store
    float invA = 1.f / lA, invB = 1.f / lB;
    #pragma unroll
    for (int jn = 0; jn < 8; jn++) {
        int col = h * DH + jn * 8 + qd * 2;
        size_t oA = ((size_t)b * SS + sA) * DD + col;
        size_t oB = ((size_t)b * SS + sB) * DD + col;
        __nv_bfloat16 h0,l0,h1,l1;
        split_bf16(oacc[jn][0] * invA, h0, l0);
        split_bf16(oacc[jn][1] * invA, h1, l1);
        *(__nv_bfloat162*)(Oh + oA) = __halves2bfloat162(h0, h1);
        *(__nv_bfloat162*)(Ol + oA) = __halves2bfloat162(l0, l1);
        split_bf16(oacc[jn][2] * invB, h0, l0);
        split_bf16(oacc[jn][3] * invB, h1, l1);
        *(__nv_bfloat162*)(Oh + oB) = __halves2bfloat162(h0, h1);
        *(__nv_bfloat162*)(Ol + oB) = __halves2bfloat162(l0, l1);
    }
}

// ---------------- launch ----------------------------------------------------
extern "C" void kernel_launch(void* const* d_in, const int* in_sizes, int n_in,
                              void* d_out, int out_size)
{
    (void)in_sizes; (void)n_in; (void)out_size;
    const float* x   = (const float*)d_in[0];
    const float* Wq  = (const float*)d_in[1];
    const float* bq  = (const float*)d_in[2];
    const float* Wk  = (const float*)d_in[3];
    const float* bk  = (const float*)d_in[4];
    const float* Wv  = (const float*)d_in[5];
    const float* bv  = (const float*)d_in[6];
    const float* Wo  = (const float*)d_in[7];
    const float* bo  = (const float*)d_in[8];
    const float* Er  = (const float*)d_in[9];
    const float* W1  = (const float*)d_in[10];
    const float* b1  = (const float*)d_in[11];
    const float* W2  = (const float*)d_in[12];
    const float* b2  = (const float*)d_in[13];
    const float* g1  = (const float*)d_in[14];
    const float* be1 = (const float*)d_in[15];
    const float* g2  = (const float*)d_in[16];
    const float* be2 = (const float*)d_in[17];
    float* y = (float*)d_out;

    float *px1, *prel, *px2, *px3;
    cudaGetSymbolAddress((void**)&px1,  g_x1);
    cudaGetSymbolAddress((void**)&prel, g_rel);
    cudaGetSymbolAddress((void**)&px2,  g_x2);
    cudaGetSymbolAddress((void**)&px3,  g_x3);

    __nv_bfloat16 *x1h,*x1l,*x3h,*x3l,*qh,*ql,*kh,*kl,*vh,*vl,*avh,*avl,*h1h,*h1l,*erh,*erl;
    __nv_bfloat16 *wqh,*wql,*wkh,*wkl,*wvh,*wvl,*woh,*wol,*w1h,*w1l,*w2h,*w2l;
    cudaGetSymbolAddress((void**)&x1h, g_x1h); cudaGetSymbolAddress((void**)&x1l, g_x1l);
    cudaGetSymbolAddress((void**)&x3h, g_x3h); cudaGetSymbolAddress((void**)&x3l, g_x3l);
    cudaGetSymbolAddress((void**)&qh,  g_qh);  cudaGetSymbolAddress((void**)&ql,  g_ql);
    cudaGetSymbolAddress((void**)&kh,  g_kh);  cudaGetSymbolAddress((void**)&kl,  g_kl);
    cudaGetSymbolAddress((void**)&vh,  g_vh);  cudaGetSymbolAddress((void**)&vl,  g_vl);
    cudaGetSymbolAddress((void**)&avh, g_avh); cudaGetSymbolAddress((void**)&avl, g_avl);
    cudaGetSymbolAddress((void**)&h1h, g_h1h); cudaGetSymbolAddress((void**)&h1l, g_h1l);
    cudaGetSymbolAddress((void**)&erh, g_erh); cudaGetSymbolAddress((void**)&erl, g_erl);
    cudaGetSymbolAddress((void**)&wqh, g_wqh); cudaGetSymbolAddress((void**)&wql, g_wql);
    cudaGetSymbolAddress((void**)&wkh, g_wkh); cudaGetSymbolAddress((void**)&wkl, g_wkl);
    cudaGetSymbolAddress((void**)&wvh, g_wvh); cudaGetSymbolAddress((void**)&wvl, g_wvl);
    cudaGetSymbolAddress((void**)&woh, g_woh); cudaGetSymbolAddress((void**)&wol, g_wol);
    cudaGetSymbolAddress((void**)&w1h, g_w1h); cudaGetSymbolAddress((void**)&w1l, g_w1l);
    cudaGetSymbolAddress((void**)&w2h, g_w2h); cudaGetSymbolAddress((void**)&w2l, g_w2l);

    cudaFuncSetAttribute(gemm_mma<0,false,true>,  cudaFuncAttributeMaxDynamicSharedMemorySize, GEMM_SMEM);
    cudaFuncSetAttribute(gemm_mma<1,false,false>, cudaFuncAttributeMaxDynamicSharedMemorySize, GEMM_SMEM);
    cudaFuncSetAttribute(gemm_mma<1,true,false>,  cudaFuncAttributeMaxDynamicSharedMemorySize, GEMM_SMEM);
    cudaFuncSetAttribute(rel_mma,   cudaFuncAttributeMaxDynamicSharedMemorySize, REL_SMEM);
    cudaFuncSetAttribute(flash_mma, cudaFuncAttributeMaxDynamicSharedMemorySize, FL_SMEM);

    // weight transpose + split
    convBT<<<dim3(DD/32, DD/32), 256>>>(Wq, wqh, wql, DD, DD);
    convBT<<<dim3(DD/32, DD/32), 256>>>(Wk, wkh, wkl, DD, DD);
    convBT<<<dim3(DD/32, DD/32), 256>>>(Wv, wvh, wvl, DD, DD);
    convBT<<<dim3(DD/32, DD/32), 256>>>(Wo, woh, wol, DD, DD);
    convBT<<<dim3(FF/32, DD/32), 256>>>(W1, w1h, w1l, DD, FF);
    convBT<<<dim3(DD/32, FF/32), 256>>>(W2, w2h, w2l, FF, DD);
    splitE<<<(SS*DH + 1023)/1024, 256>>>(Er, erh, erl, SS*DH);

    // x1 = LN(x)
    ln_kernel<<<MM, 256>>>(x, g1, be1, px1, x1h, x1l);
    // q/k/v -> bf16 hi/lo
    gemm_mma<1,false,false><<<dim3(DD/128, MM/128), 256, GEMM_SMEM>>>(
        x1h, x1l, wqh, wql, bq, nullptr, nullptr, qh, ql, DD, DD, 0.125f);
    gemm_mma<1,false,false><<<dim3(DD/128, MM/128), 256, GEMM_SMEM>>>(
        x1h, x1l, wkh, wkl, bk, nullptr, nullptr, kh, kl, DD, DD, 1.f);
    gemm_mma<1,false,false><<<dim3(DD/128, MM/128), 256, GEMM_SMEM>>>(
        x1h, x1l, wvh, wvl, bv, nullptr, nullptr, vh, vl, DD, DD, 1.f);
    // rel = q@Er^T (band tiles)
    rel_mma<<<dim3(SS/128, SS/128, BB*HH), 256, REL_SMEM>>>(qh, ql, erh, erl, prel);
    // fused attention
    flash_mma<<<dim3(SS/128, BB*HH), 256, FL_SMEM>>>(
        qh, ql, kh, kl, vh, vl, prel, avh, avl);
    // x2 = x1 + av@Wo + bo
    gemm_mma<0,false,true><<<dim3(DD/128, MM/128), 256, GEMM_SMEM>>>(
        avh, avl, woh, wol, bo, px1, px2, nullptr, nullptr, DD, DD, 1.f);
    // x3 = LN(x2)
    ln_kernel<<<MM, 256>>>(px2, g2, be2, px3, x3h, x3l);
    // h1 = relu(x3@W1+b1)
    gemm_mma<1,true,false><<<dim3(FF/128, MM/128), 256, GEMM_SMEM>>>(
        x3h, x3l, w1h, w1l, b1, nullptr, nullptr, h1h, h1l, FF, DD, 1.f);
    // y = x3 + h1@W2 + b2
    gemm_mma<0,false,true><<<dim3(DD/128, MM/128), 256, GEMM_SMEM>>>(
        h1h, h1l, w2h, w2l, b2, px3, y, nullptr, nullptr, DD, FF, 1.f);
}

// round 7
// speedup vs baseline: 1.0677x; 1.0677x over previous
#include <cuda_runtime.h>
#include <cuda_bf16.h>
#include <math.h>
#include <stdint.h>

#define BB 2
#define SS 2048
#define DD 1024
#define HH 16
#define DH 64
#define FF 4096
#define MM (BB*SS)   // 4096 rows

// ---------------- scratch (device globals; no allocation allowed) ----------
__device__ float g_x1 [MM*DD];
__device__ float g_rel[(size_t)BB*HH*SS*SS];   // q@Er^T (upper band tiles only)
__device__ float g_x2 [MM*DD];
__device__ float g_x3 [MM*DD];

__device__ __nv_bfloat16 g_x1h[MM*DD],  g_x1l[MM*DD];
__device__ __nv_bfloat16 g_x3h[MM*DD],  g_x3l[MM*DD];
__device__ __nv_bfloat16 g_qh [MM*DD],  g_ql [MM*DD];
__device__ __nv_bfloat16 g_kh [MM*DD],  g_kl [MM*DD];
__device__ __nv_bfloat16 g_vh [MM*DD],  g_vl [MM*DD];
__device__ __nv_bfloat16 g_avh[MM*DD],  g_avl[MM*DD];
__device__ __nv_bfloat16 g_h1h[(size_t)MM*FF], g_h1l[(size_t)MM*FF];
__device__ __nv_bfloat16 g_erh[SS*DH], g_erl[SS*DH];
__device__ __nv_bfloat16 g_wqh[DD*DD], g_wql[DD*DD];
__device__ __nv_bfloat16 g_wkh[DD*DD], g_wkl[DD*DD];
__device__ __nv_bfloat16 g_wvh[DD*DD], g_wvl[DD*DD];
__device__ __nv_bfloat16 g_woh[DD*DD], g_wol[DD*DD];
__device__ __nv_bfloat16 g_w1h[(size_t)DD*FF], g_w1l[(size_t)DD*FF];
__device__ __nv_bfloat16 g_w2h[(size_t)DD*FF], g_w2l[(size_t)DD*FF];

// ======================= helpers ============================================
__device__ __forceinline__ uint32_t smem_u32(const void* p) {
    uint32_t a;
    asm("{ .reg .u64 t; cvta.to.shared.u64 t, %1; cvt.u32.u64 %0, t; }"
        : "=r"(a) : "l"(p));
    return a;
}
__device__ __forceinline__ void ldsm4(uint32_t* r, uint32_t addr) {
    asm volatile("ldmatrix.sync.aligned.m8n8.x4.shared.b16 {%0,%1,%2,%3}, [%4];"
        : "=r"(r[0]), "=r"(r[1]), "=r"(r[2]), "=r"(r[3]) : "r"(addr));
}
__device__ __forceinline__ void ldsm4t(uint32_t* r, uint32_t addr) {
    asm volatile("ldmatrix.sync.aligned.m8n8.x4.trans.shared.b16 {%0,%1,%2,%3}, [%4];"
        : "=r"(r[0]), "=r"(r[1]), "=r"(r[2]), "=r"(r[3]) : "r"(addr));
}
__device__ __forceinline__ void mma_bf16(float* c, const uint32_t* a, const uint32_t* b) {
    asm volatile("mma.sync.aligned.m16n8k16.row.col.f32.bf16.bf16.f32 "
        "{%0,%1,%2,%3}, {%4,%5,%6,%7}, {%8,%9}, {%0,%1,%2,%3};"
        : "+f"(c[0]), "+f"(c[1]), "+f"(c[2]), "+f"(c[3])
        : "r"(a[0]), "r"(a[1]), "r"(a[2]), "r"(a[3]), "r"(b[0]), "r"(b[1]));
}
__device__ __forceinline__ void split_bf16(float v, __nv_bfloat16& h, __nv_bfloat16& l) {
    h = __float2bfloat16(v);
    l = __float2bfloat16(v - __bfloat162float(h));
}
__device__ __forceinline__ void pack_split(float x, float y, uint32_t& hi, uint32_t& lo) {
    __nv_bfloat16 xh = __float2bfloat16(x), yh = __float2bfloat16(y);
    __nv_bfloat16 xl = __float2bfloat16(x - __bfloat162float(xh));
    __nv_bfloat16 yl = __float2bfloat16(y - __bfloat162float(yh));
    __nv_bfloat162 a = __halves2bfloat162(xh, yh);
    __nv_bfloat162 b = __halves2bfloat162(xl, yl);
    hi = *(uint32_t*)&a; lo = *(uint32_t*)&b;
}

#define RSTR 144
#define ASZ (128 * RSTR)          // 18432 B per 128x64-bf16 array
#define QSZ (64 * RSTR)           // 9216 B per 64x64-bf16 array

// ================== weight transpose + bf16 split: [K][N]->[N][K] ===========
__global__ __launch_bounds__(256) void convBT(
    const float* __restrict__ W, __nv_bfloat16* __restrict__ Th,
    __nv_bfloat16* __restrict__ Tl, int K, int N)
{
    __shared__ float ts[32][33];
    int n0 = blockIdx.x * 32, k0 = blockIdx.y * 32;
    int tx = threadIdx.x & 31, ty = threadIdx.x >> 5;
    #pragma unroll
    for (int i = 0; i < 4; i++)
        ts[ty + 8*i][tx] = W[(size_t)(k0 + ty + 8*i) * N + n0 + tx];
    __syncthreads();
    #pragma unroll
    for (int i = 0; i < 4; i++) {
        int n = ty + 8*i;
        float v = ts[tx][n];
        __nv_bfloat16 h, l; split_bf16(v, h, l);
        size_t o = (size_t)(n0 + n) * K + k0 + tx;
        Th[o] = h; Tl[o] = l;
    }
}

// -------- elementwise bf16 split (Er) ---------------------------------------
__global__ __launch_bounds__(256) void splitE(
    const float* __restrict__ X, __nv_bfloat16* __restrict__ Xh,
    __nv_bfloat16* __restrict__ Xl, int n)
{
    int i = blockIdx.x * 1024 + threadIdx.x * 4;
    if (i >= n) return;
    float4 v = *(const float4*)(X + i);
    __nv_bfloat16 h, l;
    split_bf16(v.x, h, l); Xh[i+0] = h; Xl[i+0] = l;
    split_bf16(v.y, h, l); Xh[i+1] = h; Xl[i+1] = l;
    split_bf16(v.z, h, l); Xh[i+2] = h; Xl[i+2] = l;
    split_bf16(v.w, h, l); Xh[i+3] = h; Xl[i+3] = l;
}

// ---------------- LayerNorm: fp32 out + bf16 hi/lo split --------------------
__global__ __launch_bounds__(256) void ln_kernel(
    const float* __restrict__ X, const float* __restrict__ g,
    const float* __restrict__ be, float* __restrict__ Y,
    __nv_bfloat16* __restrict__ Yh, __nv_bfloat16* __restrict__ Yl)
{
    int row = blockIdx.x;
    size_t base = (size_t)row * DD;
    int tid = threadIdx.x;
    float4 v = *(const float4*)(X + base + tid * 4);
    float s = v.x + v.y + v.z + v.w;
    float q = v.x*v.x + v.y*v.y + v.z*v.z + v.w*v.w;

    __shared__ float rs[32], rq[32];
    #pragma unroll
    for (int o = 16; o > 0; o >>= 1) {
        s += __shfl_xor_sync(0xFFFFFFFF, s, o);
        q += __shfl_xor_sync(0xFFFFFFFF, q, o);
    }
    int lane = tid & 31, w = tid >> 5;
    if (lane == 0) { rs[w] = s; rq[w] = q; }
    __syncthreads();
    if (w == 0) {
        s = (lane < 8) ? rs[lane] : 0.f;
        q = (lane < 8) ? rq[lane] : 0.f;
        #pragma unroll
        for (int o = 4; o > 0; o >>= 1) {
            s += __shfl_xor_sync(0xFFFFFFFF, s, o);
            q += __shfl_xor_sync(0xFFFFFFFF, q, o);
        }
        if (lane == 0) { rs[0] = s; rq[0] = q; }
    }
    __syncthreads();
    float mean = rs[0] * (1.f / DD);
    float var  = rq[0] * (1.f / DD) - mean * mean;
    float rstd = rsqrtf(var + 1e-5f);

    float4 gv = *(const float4*)(g  + tid * 4);
    float4 bv = *(const float4*)(be + tid * 4);
    float4 o4;
    o4.x = (v.x - mean) * rstd * gv.x + bv.x;
    o4.y = (v.y - mean) * rstd * gv.y + bv.y;
    o4.z = (v.z - mean) * rstd * gv.z + bv.z;
    o4.w = (v.w - mean) * rstd * gv.w + bv.w;
    *(float4*)(Y + base + tid * 4) = o4;

    __nv_bfloat16 h0,l0,h1,l1,h2,l2,h3,l3;
    split_bf16(o4.x, h0, l0); split_bf16(o4.y, h1, l1);
    split_bf16(o4.z, h2, l2); split_bf16(o4.w, h3, l3);
    *(__nv_bfloat162*)(Yh + base + tid*4)     = __halves2bfloat162(h0, h1);
    *(__nv_bfloat162*)(Yh + base + tid*4 + 2) = __halves2bfloat162(h2, h3);
    *(__nv_bfloat162*)(Yl + base + tid*4)     = __halves2bfloat162(l0, l1);
    *(__nv_bfloat162*)(Yl + base + tid*4 + 2) = __halves2bfloat162(l2, l3);
}

// ============== mma.sync bf16-split GEMM: C = epi(A@B^T + bias) =============
#define ASZ2 ASZ
#define SA_HI 0
#define SA_LO ASZ
#define SB_HI (2*ASZ)
#define SB_LO (3*ASZ)
#define GEMM_SMEM (4*ASZ)         // 73728 B -> 2 CTAs/SM

template<int OUTM, bool RELU, bool RES>
__global__ __launch_bounds__(256)
void gemm_mma(
    const __nv_bfloat16* __restrict__ Ah, const __nv_bfloat16* __restrict__ Al,
    const __nv_bfloat16* __restrict__ Bh, const __nv_bfloat16* __restrict__ Bl,
    const float* __restrict__ bias, const float* __restrict__ res,
    float* __restrict__ Cf, __nv_bfloat16* __restrict__ Ch,
    __nv_bfloat16* __restrict__ Cl, int N, int K, float scale)
{
    extern __shared__ char smem[];
    uint32_t sb = smem_u32(smem);
    int tid = threadIdx.x;
    int lane = tid & 31, wid = tid >> 5;
    int wm = wid & 3, wn = wid >> 2;
    int m0 = blockIdx.y * 128, n0 = blockIdx.x * 128;

    int aRow = wm * 32 + ((lane >> 3) & 1) * 8 + (lane & 7);
    uint32_t aOff = (uint32_t)aRow * RSTR + ((lane >> 4) & 1) * 16;
    int bRow = wn * 64 + ((lane >> 4) & 1) * 8 + (lane & 7);
    uint32_t bOff = (uint32_t)bRow * RSTR + ((lane >> 3) & 1) * 16;

    float acc[2][8][4] = {};

    const int chunks = K >> 6;
    for (int c = 0; c < chunks; c++) {
        size_t koff = (size_t)c * 64;
        #pragma unroll
        for (int i = 0; i < 4; i++) {
            int u = tid + i * 256;
            int row = u >> 3, seg = u & 7;
            uint32_t d = (uint32_t)row * RSTR + seg * 16;
            *(uint4*)(smem + SA_HI + d) = *((const uint4*)(Ah + (size_t)(m0+row)*K + koff) + seg);
            *(uint4*)(smem + SA_LO + d) = *((const uint4*)(Al + (size_t)(m0+row)*K + koff) + seg);
            *(uint4*)(smem + SB_HI + d) = *((const uint4*)(Bh + (size_t)(n0+row)*K + koff) + seg);
            *(uint4*)(smem + SB_LO + d) = *((const uint4*)(Bl + (size_t)(n0+row)*K + koff) + seg);
        }
        __syncthreads();

        #pragma unroll
        for (int kk = 0; kk < 4; kk++) {
            uint32_t kb = kk * 32;
            uint32_t ah[2][4], al[2][4];
            ldsm4(ah[0], sb + SA_HI + aOff + kb);
            ldsm4(ah[1], sb + SA_HI + aOff + 16*RSTR + kb);
            ldsm4(al[0], sb + SA_LO + aOff + kb);
            ldsm4(al[1], sb + SA_LO + aOff + 16*RSTR + kb);
            uint32_t bh[4][4], bl[4][4];
            #pragma unroll
            for (int jp = 0; jp < 4; jp++) {
                ldsm4(bh[jp], sb + SB_HI + bOff + (uint32_t)jp*16*RSTR + kb);
                ldsm4(bl[jp], sb + SB_LO + bOff + (uint32_t)jp*16*RSTR + kb);
            }
            #pragma unroll
            for (int im = 0; im < 2; im++)
                #pragma unroll
                for (int jn = 0; jn < 8; jn++) {
                    const uint32_t* ph = &bh[jn >> 1][(jn & 1) * 2];
                    const uint32_t* pl = &bl[jn >> 1][(jn & 1) * 2];
                    mma_bf16(acc[im][jn], ah[im], ph);
                    mma_bf16(acc[im][jn], ah[im], pl);
                    mma_bf16(acc[im][jn], al[im], ph);
                }
        }
        __syncthreads();
    }

    int r = lane >> 2, cc = (lane & 3) * 2;
    #pragma unroll
    for (int im = 0; im < 2; im++) {
        int rg0 = m0 + wm * 32 + im * 16 + r;
        #pragma unroll
        for (int jn = 0; jn < 8; jn++) {
            int col = n0 + wn * 64 + jn * 8 + cc;
            float2 bv = *(const float2*)(bias + col);
            float v0 = (acc[im][jn][0] + bv.x) * scale;
            float v1 = (acc[im][jn][1] + bv.y) * scale;
            float v2 = (acc[im][jn][2] + bv.x) * scale;
            float v3 = (acc[im][jn][3] + bv.y) * scale;
            if (RELU) {
                v0 = fmaxf(v0, 0.f); v1 = fmaxf(v1, 0.f);
                v2 = fmaxf(v2, 0.f); v3 = fmaxf(v3, 0.f);
            }
            size_t o0 = (size_t)rg0 * N + col;
            size_t o1 = (size_t)(rg0 + 8) * N + col;
            if (RES) {
                float2 r0 = *(const float2*)(res + o0);
                float2 r1 = *(const float2*)(res + o1);
                v0 += r0.x; v1 += r0.y; v2 += r1.x; v3 += r1.y;
            }
            if (OUTM == 0) {
                *(float2*)(Cf + o0) = make_float2(v0, v1);
                *(float2*)(Cf + o1) = make_float2(v2, v3);
            } else {
                __nv_bfloat16 h0,l0,h1,l1,h2,l2,h3,l3;
                split_bf16(v0, h0, l0); split_bf16(v1, h1, l1);
                split_bf16(v2, h2, l2); split_bf16(v3, h3, l3);
                *(__nv_bfloat162*)(Ch + o0) = __halves2bfloat162(h0, h1);
                *(__nv_bfloat162*)(Ch + o1) = __halves2bfloat162(h2, h3);
                *(__nv_bfloat162*)(Cl + o0) = __halves2bfloat162(l0, l1);
                *(__nv_bfloat162*)(Cl + o1) = __halves2bfloat162(l2, l3);
            }
        }
    }
}

// ========== rel = q @ Er^T, band tiles only (K = 64) ========================
__global__ __launch_bounds__(256)
void rel_mma(
    const __nv_bfloat16* __restrict__ Ah, const __nv_bfloat16* __restrict__ Al,
    const __nv_bfloat16* __restrict__ Bh, const __nv_bfloat16* __restrict__ Bl,
    float* __restrict__ out)
{
    int m0 = blockIdx.y * 128, n0 = blockIdx.x * 128;
    if (m0 + n0 + 255 < SS - 1) return;   // tile never read by skew gather
    int bh = blockIdx.z;
    int b = bh >> 4, h = bh & 15;

    extern __shared__ char smem[];
    uint32_t sb = smem_u32(smem);
    int tid = threadIdx.x;
    int lane = tid & 31, wid = tid >> 5;
    int wm = wid & 3, wn = wid >> 2;

    const __nv_bfloat16* Ahp = Ah + ((size_t)b * SS) * DD + h * DH;
    const __nv_bfloat16* Alp = Al + ((size_t)b * SS) * DD + h * DH;

    #pragma unroll
    for (int i = 0; i < 4; i++) {
        int u = tid + i * 256;
        int row = u >> 3, seg = u & 7;
        uint32_t d = (uint32_t)row * RSTR + seg * 16;
        *(uint4*)(smem + SA_HI + d) = *((const uint4*)(Ahp + (size_t)(m0+row)*DD) + seg);
        *(uint4*)(smem + SA_LO + d) = *((const uint4*)(Alp + (size_t)(m0+row)*DD) + seg);
        *(uint4*)(smem + SB_HI + d) = *((const uint4*)(Bh + (size_t)(n0+row)*DH) + seg);
        *(uint4*)(smem + SB_LO + d) = *((const uint4*)(Bl + (size_t)(n0+row)*DH) + seg);
    }
    __syncthreads();

    int aRow = wm * 32 + ((lane >> 3) & 1) * 8 + (lane & 7);
    uint32_t aOff = (uint32_t)aRow * RSTR + ((lane >> 4) & 1) * 16;
    int bRow = wn * 64 + ((lane >> 4) & 1) * 8 + (lane & 7);
    uint32_t bOff = (uint32_t)bRow * RSTR + ((lane >> 3) & 1) * 16;

    float acc[2][8][4] = {};
    #pragma unroll
    for (int kk = 0; kk < 4; kk++) {
        uint32_t kb = kk * 32;
        uint32_t ah[2][4], al[2][4];
        ldsm4(ah[0], sb + SA_HI + aOff + kb);
        ldsm4(ah[1], sb + SA_HI + aOff + 16*RSTR + kb);
        ldsm4(al[0], sb + SA_LO + aOff + kb);
        ldsm4(al[1], sb + SA_LO + aOff + 16*RSTR + kb);
        uint32_t bhf[4][4], blf[4][4];
        #pragma unroll
        for (int jp = 0; jp < 4; jp++) {
            ldsm4(bhf[jp], sb + SB_HI + bOff + (uint32_t)jp*16*RSTR + kb);
            ldsm4(blf[jp], sb + SB_LO + bOff + (uint32_t)jp*16*RSTR + kb);
        }
        #pragma unroll
        for (int im = 0; im < 2; im++)
            #pragma unroll
            for (int jn = 0; jn < 8; jn++) {
                const uint32_t* ph = &bhf[jn >> 1][(jn & 1) * 2];
                const uint32_t* pl = &blf[jn >> 1][(jn & 1) * 2];
                mma_bf16(acc[im][jn], ah[im], ph);
                mma_bf16(acc[im][jn], ah[im], pl);
                mma_bf16(acc[im][jn], al[im], ph);
            }
    }

    float* ob = out + (size_t)bh * SS * SS;
    int r = lane >> 2, cc = (lane & 3) * 2;
    #pragma unroll
    for (int im = 0; im < 2; im++) {
        int rg0 = m0 + wm * 32 + im * 16 + r;
        #pragma unroll
        for (int jn = 0; jn < 8; jn++) {
            int col = n0 + wn * 64 + jn * 8 + cc;
            *(float2*)(ob + (size_t)rg0 * SS + col)      = make_float2(acc[im][jn][0], acc[im][jn][1]);
            *(float2*)(ob + (size_t)(rg0+8) * SS + col)  = make_float2(acc[im][jn][2], acc[im][jn][3]);
        }
    }
}

// ========== flash attention: softmax(qk^T + skew(rel)) @ v ==================
// CTA: one (b,h) and 64 q-rows, 128 threads (4 warps x 16 rows).
// smem 92160 B -> 2 CTAs/SM for cross-CTA latency hiding.
#define FL_Q_HI 0
#define FL_Q_LO QSZ
#define FL_K_HI (2*QSZ)
#define FL_K_LO (2*QSZ + ASZ)
#define FL_V_HI (2*QSZ + 2*ASZ)
#define FL_V_LO (2*QSZ + 3*ASZ)
#define FL_SMEM (2*QSZ + 4*ASZ)    // 92160 B

__global__ __launch_bounds__(128)
void flash_mma(
    const __nv_bfloat16* __restrict__ Qh, const __nv_bfloat16* __restrict__ Ql,
    const __nv_bfloat16* __restrict__ Kh, const __nv_bfloat16* __restrict__ Kl,
    const __nv_bfloat16* __restrict__ Vh, const __nv_bfloat16* __restrict__ Vl,
    const float* __restrict__ REL,
    __nv_bfloat16* __restrict__ Oh, __nv_bfloat16* __restrict__ Ol)
{
    extern __shared__ char smem[];
    uint32_t sb = smem_u32(smem);
    int tid = threadIdx.x;
    int lane = tid & 31, w = tid >> 5;     // 4 warps
    int s0 = blockIdx.x * 64;
    int bh = blockIdx.y;
    int b = bh >> 4, h = bh & 15;

    const __nv_bfloat16* qhb = Qh + ((size_t)b * SS) * DD + h * DH;
    const __nv_bfloat16* qlb = Ql + ((size_t)b * SS) * DD + h * DH;
    const __nv_bfloat16* khb = Kh + ((size_t)b * SS) * DD + h * DH;
    const __nv_bfloat16* klb = Kl + ((size_t)b * SS) * DD + h * DH;
    const __nv_bfloat16* vhb = Vh + ((size_t)b * SS) * DD + h * DH;
    const __nv_bfloat16* vlb = Vl + ((size_t)b * SS) * DD + h * DH;

    // stage Q (64 rows, persistent in smem)
    #pragma unroll
    for (int i = 0; i < 4; i++) {
        int u = tid + i * 128;
        int row = u >> 3, seg = u & 7;
        uint32_t d = (uint32_t)row * RSTR + seg * 16;
        *(uint4*)(smem + FL_Q_HI + d) = *((const uint4*)(qhb + (size_t)(s0+row)*DD) + seg);
        *(uint4*)(smem + FL_Q_LO + d) = *((const uint4*)(qlb + (size_t)(s0+row)*DD) + seg);
    }

    int g = lane >> 2, qd = lane & 3;
    int sA = s0 + w * 16 + g;
    int sB = sA + 8;
    const float* rpA = REL + ((size_t)bh * SS + sA) * SS + (SS - 1 - sA);
    const float* rpB = REL + ((size_t)bh * SS + sB) * SS + (SS - 1 - sB);

    uint32_t aOff = (uint32_t)(w*16 + ((lane>>3)&1)*8 + (lane&7)) * RSTR + ((lane>>4)&1)*16;
    uint32_t bOff = (uint32_t)(((lane>>4)&1)*8 + (lane&7)) * RSTR + ((lane>>3)&1)*16;
    uint32_t vKr = ((lane>>3)&1)*8 + (lane&7);
    uint32_t vCb = ((lane>>4)&1)*16;

    float oacc[8][4] = {};
    float mA = -1e30f, mB = -1e30f, lA = 0.f, lB = 0.f;

    for (int c = 0; c < SS/128; c++) {
        int t0 = c * 128;
        __syncthreads();    // protect K/V smem reuse (and Q store on c==0)
        #pragma unroll
        for (int i = 0; i < 8; i++) {
            int u = tid + i * 128;
            int row = u >> 3, seg = u & 7;
            uint32_t d = (uint32_t)row * RSTR + seg * 16;
            *(uint4*)(smem + FL_K_HI + d) = *((const uint4*)(khb + (size_t)(t0+row)*DD) + seg);
            *(uint4*)(smem + FL_K_LO + d) = *((const uint4*)(klb + (size_t)(t0+row)*DD) + seg);
            *(uint4*)(smem + FL_V_HI + d) = *((const uint4*)(vhb + (size_t)(t0+row)*DD) + seg);
            *(uint4*)(smem + FL_V_LO + d) = *((const uint4*)(vlb + (size_t)(t0+row)*DD) + seg);
        }
        __syncthreads();

        // S = q @ k^T (3-term split), 16 n-tiles of 8 cols
        float sacc[16][4] = {};
        #pragma unroll
        for (int kk = 0; kk < 4; kk++) {
            uint32_t kb = kk * 32;
            uint32_t ah[4], al[4];
            ldsm4(ah, sb + FL_Q_HI + aOff + kb);
            ldsm4(al, sb + FL_Q_LO + aOff + kb);
            #pragma unroll
            for (int jp = 0; jp < 8; jp++) {
                uint32_t bhf[4], blf[4];
                ldsm4(bhf, sb + FL_K_HI + bOff + (uint32_t)jp*16*RSTR + kb);
                ldsm4(blf, sb + FL_K_LO + bOff + (uint32_t)jp*16*RSTR + kb);
                #pragma unroll
                for (int e = 0; e < 2; e++) {
                    int jn = jp * 2 + e;
                    mma_bf16(sacc[jn], ah, &bhf[e*2]);
                    mma_bf16(sacc[jn], ah, &blf[e*2]);
                    mma_bf16(sacc[jn], al, &bhf[e*2]);
                }
            }
        }

        // skew add: sacc[jn][0,1] row sA, [2,3] row sB, cols t0+8jn+2qd(+1)
        if (t0 <= sA) {
            #pragma unroll
            for (int jn = 0; jn < 16; jn++) {
                int t = t0 + jn * 8 + qd * 2;
                if (t     <= sA) sacc[jn][0] += __ldg(rpA + t);
                if (t + 1 <= sA) sacc[jn][1] += __ldg(rpA + t + 1);
            }
        }
        if (t0 <= sB) {
            #pragma unroll
            for (int jn = 0; jn < 16; jn++) {
                int t = t0 + jn * 8 + qd * 2;
                if (t     <= sB) sacc[jn][2] += __ldg(rpB + t);
                if (t + 1 <= sB) sacc[jn][3] += __ldg(rpB + t + 1);
            }
        }

        // online softmax
        float cmA = -1e30f, cmB = -1e30f;
        #pragma unroll
        for (int jn = 0; jn < 16; jn++) {
            cmA = fmaxf(cmA, fmaxf(sacc[jn][0], sacc[jn][1]));
            cmB = fmaxf(cmB, fmaxf(sacc[jn][2], sacc[jn][3]));
        }
        cmA = fmaxf(cmA, __shfl_xor_sync(0xFFFFFFFF, cmA, 1));
        cmA = fmaxf(cmA, __shfl_xor_sync(0xFFFFFFFF, cmA, 2));
        cmB = fmaxf(cmB, __shfl_xor_sync(0xFFFFFFFF, cmB, 1));
        cmB = fmaxf(cmB, __shfl_xor_sync(0xFFFFFFFF, cmB, 2));
        float mnA = fmaxf(mA, cmA), mnB = fmaxf(mB, cmB);
        float alA = __expf(mA - mnA), alB = __expf(mB - mnB);
        mA = mnA; mB = mnB;

        float suA = 0.f, suB = 0.f;
        #pragma unroll
        for (int jn = 0; jn < 16; jn++) {
            sacc[jn][0] = __expf(sacc[jn][0] - mnA);
            sacc[jn][1] = __expf(sacc[jn][1] - mnA);
            sacc[jn][2] = __expf(sacc[jn][2] - mnB);
            sacc[jn][3] = __expf(sacc[jn][3] - mnB);
            suA += sacc[jn][0] + sacc[jn][1];
            suB += sacc[jn][2] + sacc[jn][3];
        }
        suA += __shfl_xor_sync(0xFFFFFFFF, suA, 1);
        suA += __shfl_xor_sync(0xFFFFFFFF, suA, 2);
        suB += __shfl_xor_sync(0xFFFFFFFF, suB, 1);
        suB += __shfl_xor_sync(0xFFFFFFFF, suB, 2);
        lA = lA * alA + suA;
        lB = lB * alB + suB;

        // rescale O
        #pragma unroll
        for (int jn = 0; jn < 8; jn++) {
            oacc[jn][0] *= alA; oacc[jn][1] *= alA;
            oacc[jn][2] *= alB; oacc[jn][3] *= alB;
        }

        // O += P @ V (3-term), 8 k-steps of 16
        #pragma unroll
        for (int k2 = 0; k2 < 8; k2++) {
            uint32_t pah[4], pal[4];
            pack_split(sacc[2*k2][0],   sacc[2*k2][1],   pah[0], pal[0]);
            pack_split(sacc[2*k2][2],   sacc[2*k2][3],   pah[1], pal[1]);
            pack_split(sacc[2*k2+1][0], sacc[2*k2+1][1], pah[2], pal[2]);
            pack_split(sacc[2*k2+1][2], sacc[2*k2+1][3], pah[3], pal[3]);
            uint32_t vRowOff = (uint32_t)(k2 * 16 + vKr) * RSTR;
            #pragma unroll
            for (int jp = 0; jp < 4; jp++) {
                uint32_t vh4[4], vl4[4];
                ldsm4t(vh4, sb + FL_V_HI + vRowOff + vCb + jp * 32);
                ldsm4t(vl4, sb + FL_V_LO + vRowOff + vCb + jp * 32);
                #pragma unroll
                for (int e = 0; e < 2; e++) {
                    int jo = jp * 2 + e;
                    mma_bf16(oacc[jo], pah, &vh4[e*2]);
                    mma_bf16(oacc[jo], pah, &vl4[e*2]);
                    mma_bf16(oacc[jo], pal, &vh4[e*2]);
                }
            }
        }
    }

    // epilogue: normalize + split store
    float invA = 1.f / lA, invB = 1.f / lB;
    #pragma unroll
    for (int jn = 0; jn < 8; jn++) {
        int col = h * DH + jn * 8 + qd * 2;
        size_t oA = ((size_t)b * SS + sA) * DD + col;
        size_t oB = ((size_t)b * SS + sB) * DD + col;
        __nv_bfloat16 h0,l0,h1,l1;
        split_bf16(oacc[jn][0] * invA, h0, l0);
        split_bf16(oacc[jn][1] * invA, h1, l1);
        *(__nv_bfloat162*)(Oh + oA) = __halves2bfloat162(h0, h1);
        *(__nv_bfloat162*)(Ol + oA) = __halves2bfloat162(l0, l1);
        split_bf16(oacc[jn][2] * invB, h0, l0);
        split_bf16(oacc[jn][3] * invB, h1, l1);
        *(__nv_bfloat162*)(Oh + oB) = __halves2bfloat162(h0, h1);
        *(__nv_bfloat162*)(Ol + oB) = __halves2bfloat162(l0, l1);
    }
}

// ---------------- launch ----------------------------------------------------
extern "C" void kernel_launch(void* const* d_in, const int* in_sizes, int n_in,
                              void* d_out, int out_size)
{
    (void)in_sizes; (void)n_in; (void)out_size;
    const float* x   = (const float*)d_in[0];
    const float* Wq  = (const float*)d_in[1];
    const float* bq  = (const float*)d_in[2];
    const float* Wk  = (const float*)d_in[3];
    const float* bk  = (const float*)d_in[4];
    const float* Wv  = (const float*)d_in[5];
    const float* bv  = (const float*)d_in[6];
    const float* Wo  = (const float*)d_in[7];
    const float* bo  = (const float*)d_in[8];
    const float* Er  = (const float*)d_in[9];
    const float* W1  = (const float*)d_in[10];
    const float* b1  = (const float*)d_in[11];
    const float* W2  = (const float*)d_in[12];
    const float* b2  = (const float*)d_in[13];
    const float* g1  = (const float*)d_in[14];
    const float* be1 = (const float*)d_in[15];
    const float* g2  = (const float*)d_in[16];
    const float* be2 = (const float*)d_in[17];
    float* y = (float*)d_out;

    float *px1, *prel, *px2, *px3;
    cudaGetSymbolAddress((void**)&px1,  g_x1);
    cudaGetSymbolAddress((void**)&prel, g_rel);
    cudaGetSymbolAddress((void**)&px2,  g_x2);
    cudaGetSymbolAddress((void**)&px3,  g_x3);

    __nv_bfloat16 *x1h,*x1l,*x3h,*x3l,*qh,*ql,*kh,*kl,*vh,*vl,*avh,*avl,*h1h,*h1l,*erh,*erl;
    __nv_bfloat16 *wqh,*wql,*wkh,*wkl,*wvh,*wvl,*woh,*wol,*w1h,*w1l,*w2h,*w2l;
    cudaGetSymbolAddress((void**)&x1h, g_x1h); cudaGetSymbolAddress((void**)&x1l, g_x1l);
    cudaGetSymbolAddress((void**)&x3h, g_x3h); cudaGetSymbolAddress((void**)&x3l, g_x3l);
    cudaGetSymbolAddress((void**)&qh,  g_qh);  cudaGetSymbolAddress((void**)&ql,  g_ql);
    cudaGetSymbolAddress((void**)&kh,  g_kh);  cudaGetSymbolAddress((void**)&kl,  g_kl);
    cudaGetSymbolAddress((void**)&vh,  g_vh);  cudaGetSymbolAddress((void**)&vl,  g_vl);
    cudaGetSymbolAddress((void**)&avh, g_avh); cudaGetSymbolAddress((void**)&avl, g_avl);
    cudaGetSymbolAddress((void**)&h1h, g_h1h); cudaGetSymbolAddress((void**)&h1l, g_h1l);
    cudaGetSymbolAddress((void**)&erh, g_erh); cudaGetSymbolAddress((void**)&erl, g_erl);
    cudaGetSymbolAddress((void**)&wqh, g_wqh); cudaGetSymbolAddress((void**)&wql, g_wql);
    cudaGetSymbolAddress((void**)&wkh, g_wkh); cudaGetSymbolAddress((void**)&wkl, g_wkl);
    cudaGetSymbolAddress((void**)&wvh, g_wvh); cudaGetSymbolAddress((void**)&wvl, g_wvl);
    cudaGetSymbolAddress((void**)&woh, g_woh); cudaGetSymbolAddress((void**)&wol, g_wol);
    cudaGetSymbolAddress((void**)&w1h, g_w1h); cudaGetSymbolAddress((void**)&w1l, g_w1l);
    cudaGetSymbolAddress((void**)&w2h, g_w2h); cudaGetSymbolAddress((void**)&w2l, g_w2l);

    cudaFuncSetAttribute(gemm_mma<0,false,true>,  cudaFuncAttributeMaxDynamicSharedMemorySize, GEMM_SMEM);
    cudaFuncSetAttribute(gemm_mma<1,false,false>, cudaFuncAttributeMaxDynamicSharedMemorySize, GEMM_SMEM);
    cudaFuncSetAttribute(gemm_mma<1,true,false>,  cudaFuncAttributeMaxDynamicSharedMemorySize, GEMM_SMEM);
    cudaFuncSetAttribute(rel_mma,   cudaFuncAttributeMaxDynamicSharedMemorySize, GEMM_SMEM);
    cudaFuncSetAttribute(flash_mma, cudaFuncAttributeMaxDynamicSharedMemorySize, FL_SMEM);

    // weight transpose + split
    convBT<<<dim3(DD/32, DD/32), 256>>>(Wq, wqh, wql, DD, DD);
    convBT<<<dim3(DD/32, DD/32), 256>>>(Wk, wkh, wkl, DD, DD);
    convBT<<<dim3(DD/32, DD/32), 256>>>(Wv, wvh, wvl, DD, DD);
    convBT<<<dim3(DD/32, DD/32), 256>>>(Wo, woh, wol, DD, DD);
    convBT<<<dim3(FF/32, DD/32), 256>>>(W1, w1h, w1l, DD, FF);
    convBT<<<dim3(DD/32, FF/32), 256>>>(W2, w2h, w2l, FF, DD);
    splitE<<<(SS*DH + 1023)/1024, 256>>>(Er, erh, erl, SS*DH);

    // x1 = LN(x)
    ln_kernel<<<MM, 256>>>(x, g1, be1, px1, x1h, x1l);
    // q/k/v -> bf16 hi/lo
    gemm_mma<1,false,false><<<dim3(DD/128, MM/128), 256, GEMM_SMEM>>>(
        x1h, x1l, wqh, wql, bq, nullptr, nullptr, qh, ql, DD, DD, 0.125f);
    gemm_mma<1,false,false><<<dim3(DD/128, MM/128), 256, GEMM_SMEM>>>(
        x1h, x1l, wkh, wkl, bk, nullptr, nullptr, kh, kl, DD, DD, 1.f);
    gemm_mma<1,false,false><<<dim3(DD/128, MM/128), 256, GEMM_SMEM>>>(
        x1h, x1l, wvh, wvl, bv, nullptr, nullptr, vh, vl, DD, DD, 1.f);
    // rel = q@Er^T (band tiles)
    rel_mma<<<dim3(SS/128, SS/128, BB*HH), 256, GEMM_SMEM>>>(qh, ql, erh, erl, prel);
    // fused attention (64-row q tiles, 2 CTAs/SM)
    flash_mma<<<dim3(SS/64, BB*HH), 128, FL_SMEM>>>(
        qh, ql, kh, kl, vh, vl, prel, avh, avl);
    // x2 = x1 + av@Wo + bo
    gemm_mma<0,false,true><<<dim3(DD/128, MM/128), 256, GEMM_SMEM>>>(
        avh, avl, woh, wol, bo, px1, px2, nullptr, nullptr, DD, DD, 1.f);
    // x3 = LN(x2)
    ln_kernel<<<MM, 256>>>(px2, g2, be2, px3, x3h, x3l);
    // h1 = relu(x3@W1+b1)
    gemm_mma<1,true,false><<<dim3(FF/128, MM/128), 256, GEMM_SMEM>>>(
        x3h, x3l, w1h, w1l, b1, nullptr, nullptr, h1h, h1l, FF, DD, 1.f);
    // y = x3 + h1@W2 + b2
    gemm_mma<0,false,true><<<dim3(DD/128, MM/128), 256, GEMM_SMEM>>>(
        h1h, h1l, w2h, w2l, b2, px3, y, nullptr, nullptr, DD, FF, 1.f);
}

// round 8
// speedup vs baseline: 1.3397x; 1.2548x over previous
#include <cuda_runtime.h>
#include <cuda_bf16.h>
#include <cuda_fp16.h>
#include <math.h>
#include <stdint.h>

#define BB 2
#define SS 2048
#define DD 1024
#define HH 16
#define DH 64
#define FF 4096
#define MM (BB*SS)   // 4096 rows

// ---------------- scratch (device globals; no allocation allowed) ----------
__device__ float g_x1 [MM*DD];
__device__ float g_rel[(size_t)BB*HH*SS*SS];   // q@Er^T (upper band tiles only)
__device__ float g_x2 [MM*DD];
__device__ float g_x3 [MM*DD];

__device__ __nv_bfloat16 g_x1h[MM*DD],  g_x1l[MM*DD];
__device__ __nv_bfloat16 g_x3h[MM*DD],  g_x3l[MM*DD];
__device__ __half        g_qf [MM*DD];
__device__ __half        g_kf [MM*DD];
__device__ __half        g_vf [MM*DD];
__device__ __nv_bfloat16 g_avh[MM*DD],  g_avl[MM*DD];
__device__ __nv_bfloat16 g_h1h[(size_t)MM*FF], g_h1l[(size_t)MM*FF];
__device__ __half        g_erf[SS*DH];
__device__ __nv_bfloat16 g_wqh[DD*DD], g_wql[DD*DD];
__device__ __nv_bfloat16 g_wkh[DD*DD], g_wkl[DD*DD];
__device__ __nv_bfloat16 g_wvh[DD*DD], g_wvl[DD*DD];
__device__ __nv_bfloat16 g_woh[DD*DD], g_wol[DD*DD];
__device__ __nv_bfloat16 g_w1h[(size_t)DD*FF], g_w1l[(size_t)DD*FF];
__device__ __nv_bfloat16 g_w2h[(size_t)DD*FF], g_w2l[(size_t)DD*FF];

// ======================= helpers ============================================
__device__ __forceinline__ uint32_t smem_u32(const void* p) {
    uint32_t a;
    asm("{ .reg .u64 t; cvta.to.shared.u64 t, %1; cvt.u32.u64 %0, t; }"
        : "=r"(a) : "l"(p));
    return a;
}
__device__ __forceinline__ void ldsm4(uint32_t* r, uint32_t addr) {
    asm volatile("ldmatrix.sync.aligned.m8n8.x4.shared.b16 {%0,%1,%2,%3}, [%4];"
        : "=r"(r[0]), "=r"(r[1]), "=r"(r[2]), "=r"(r[3]) : "r"(addr));
}
__device__ __forceinline__ void ldsm4t(uint32_t* r, uint32_t addr) {
    asm volatile("ldmatrix.sync.aligned.m8n8.x4.trans.shared.b16 {%0,%1,%2,%3}, [%4];"
        : "=r"(r[0]), "=r"(r[1]), "=r"(r[2]), "=r"(r[3]) : "r"(addr));
}
__device__ __forceinline__ void mma_bf16(float* c, const uint32_t* a, const uint32_t* b) {
    asm volatile("mma.sync.aligned.m16n8k16.row.col.f32.bf16.bf16.f32 "
        "{%0,%1,%2,%3}, {%4,%5,%6,%7}, {%8,%9}, {%0,%1,%2,%3};"
        : "+f"(c[0]), "+f"(c[1]), "+f"(c[2]), "+f"(c[3])
        : "r"(a[0]), "r"(a[1]), "r"(a[2]), "r"(a[3]), "r"(b[0]), "r"(b[1]));
}
__device__ __forceinline__ void mma_f16(float* c, const uint32_t* a, const uint32_t* b) {
    asm volatile("mma.sync.aligned.m16n8k16.row.col.f32.f16.f16.f32 "
        "{%0,%1,%2,%3}, {%4,%5,%6,%7}, {%8,%9}, {%0,%1,%2,%3};"
        : "+f"(c[0]), "+f"(c[1]), "+f"(c[2]), "+f"(c[3])
        : "r"(a[0]), "r"(a[1]), "r"(a[2]), "r"(a[3]), "r"(b[0]), "r"(b[1]));
}
__device__ __forceinline__ void split_bf16(float v, __nv_bfloat16& h, __nv_bfloat16& l) {
    h = __float2bfloat16(v);
    l = __float2bfloat16(v - __bfloat162float(h));
}
__device__ __forceinline__ uint32_t pack_f16(float x, float y) {
    __half2 h = __floats2half2_rn(x, y);
    return *(uint32_t*)&h;
}

#define RSTR 144
#define ASZ (128 * RSTR)          // 18432 B per 128x64 16-bit array
#define QSZ (64 * RSTR)           // 9216 B per 64x64 16-bit array

// ================== weight transpose + bf16 split: [K][N]->[N][K] ===========
__global__ __launch_bounds__(256) void convBT(
    const float* __restrict__ W, __nv_bfloat16* __restrict__ Th,
    __nv_bfloat16* __restrict__ Tl, int K, int N)
{
    __shared__ float ts[32][33];
    int n0 = blockIdx.x * 32, k0 = blockIdx.y * 32;
    int tx = threadIdx.x & 31, ty = threadIdx.x >> 5;
    #pragma unroll
    for (int i = 0; i < 4; i++)
        ts[ty + 8*i][tx] = W[(size_t)(k0 + ty + 8*i) * N + n0 + tx];
    __syncthreads();
    #pragma unroll
    for (int i = 0; i < 4; i++) {
        int n = ty + 8*i;
        float v = ts[tx][n];
        __nv_bfloat16 h, l; split_bf16(v, h, l);
        size_t o = (size_t)(n0 + n) * K + k0 + tx;
        Th[o] = h; Tl[o] = l;
    }
}

// -------- elementwise f16 convert (Er) ---------------------------------------
__global__ __launch_bounds__(256) void convEf(
    const float* __restrict__ X, __half* __restrict__ Xf, int n)
{
    int i = blockIdx.x * 1024 + threadIdx.x * 4;
    if (i >= n) return;
    float4 v = *(const float4*)(X + i);
    *(__half2*)(Xf + i)     = __floats2half2_rn(v.x, v.y);
    *(__half2*)(Xf + i + 2) = __floats2half2_rn(v.z, v.w);
}

// ---------------- LayerNorm: fp32 out + bf16 hi/lo split --------------------
__global__ __launch_bounds__(256) void ln_kernel(
    const float* __restrict__ X, const float* __restrict__ g,
    const float* __restrict__ be, float* __restrict__ Y,
    __nv_bfloat16* __restrict__ Yh, __nv_bfloat16* __restrict__ Yl)
{
    int row = blockIdx.x;
    size_t base = (size_t)row * DD;
    int tid = threadIdx.x;
    float4 v = *(const float4*)(X + base + tid * 4);
    float s = v.x + v.y + v.z + v.w;
    float q = v.x*v.x + v.y*v.y + v.z*v.z + v.w*v.w;

    __shared__ float rs[32], rq[32];
    #pragma unroll
    for (int o = 16; o > 0; o >>= 1) {
        s += __shfl_xor_sync(0xFFFFFFFF, s, o);
        q += __shfl_xor_sync(0xFFFFFFFF, q, o);
    }
    int lane = tid & 31, w = tid >> 5;
    if (lane == 0) { rs[w] = s; rq[w] = q; }
    __syncthreads();
    if (w == 0) {
        s = (lane < 8) ? rs[lane] : 0.f;
        q = (lane < 8) ? rq[lane] : 0.f;
        #pragma unroll
        for (int o = 4; o > 0; o >>= 1) {
            s += __shfl_xor_sync(0xFFFFFFFF, s, o);
            q += __shfl_xor_sync(0xFFFFFFFF, q, o);
        }
        if (lane == 0) { rs[0] = s; rq[0] = q; }
    }
    __syncthreads();
    float mean = rs[0] * (1.f / DD);
    float var  = rq[0] * (1.f / DD) - mean * mean;
    float rstd = rsqrtf(var + 1e-5f);

    float4 gv = *(const float4*)(g  + tid * 4);
    float4 bv = *(const float4*)(be + tid * 4);
    float4 o4;
    o4.x = (v.x - mean) * rstd * gv.x + bv.x;
    o4.y = (v.y - mean) * rstd * gv.y + bv.y;
    o4.z = (v.z - mean) * rstd * gv.z + bv.z;
    o4.w = (v.w - mean) * rstd * gv.w + bv.w;
    *(float4*)(Y + base + tid * 4) = o4;

    __nv_bfloat16 h0,l0,h1,l1,h2,l2,h3,l3;
    split_bf16(o4.x, h0, l0); split_bf16(o4.y, h1, l1);
    split_bf16(o4.z, h2, l2); split_bf16(o4.w, h3, l3);
    *(__nv_bfloat162*)(Yh + base + tid*4)     = __halves2bfloat162(h0, h1);
    *(__nv_bfloat162*)(Yh + base + tid*4 + 2) = __halves2bfloat162(h2, h3);
    *(__nv_bfloat162*)(Yl + base + tid*4)     = __halves2bfloat162(l0, l1);
    *(__nv_bfloat162*)(Yl + base + tid*4 + 2) = __halves2bfloat162(l2, l3);
}

// ============== mma.sync bf16-split GEMM: C = epi(A@B^T + bias) =============
// OUTM: 0 = f32, 1 = bf16 hi/lo pair, 2 = f16 single
#define SA_HI 0
#define SA_LO ASZ
#define SB_HI (2*ASZ)
#define SB_LO (3*ASZ)
#define GEMM_SMEM (4*ASZ)         // 73728 B -> 2 CTAs/SM

template<int OUTM, bool RELU, bool RES>
__global__ __launch_bounds__(256)
void gemm_mma(
    const __nv_bfloat16* __restrict__ Ah, const __nv_bfloat16* __restrict__ Al,
    const __nv_bfloat16* __restrict__ Bh, const __nv_bfloat16* __restrict__ Bl,
    const float* __restrict__ bias, const float* __restrict__ res,
    float* __restrict__ Cf, __nv_bfloat16* __restrict__ Ch,
    __nv_bfloat16* __restrict__ Cl, __half* __restrict__ Cs,
    int N, int K, float scale)
{
    extern __shared__ char smem[];
    uint32_t sb = smem_u32(smem);
    int tid = threadIdx.x;
    int lane = tid & 31, wid = tid >> 5;
    int wm = wid & 3, wn = wid >> 2;
    int m0 = blockIdx.y * 128, n0 = blockIdx.x * 128;

    int aRow = wm * 32 + ((lane >> 3) & 1) * 8 + (lane & 7);
    uint32_t aOff = (uint32_t)aRow * RSTR + ((lane >> 4) & 1) * 16;
    int bRow = wn * 64 + ((lane >> 4) & 1) * 8 + (lane & 7);
    uint32_t bOff = (uint32_t)bRow * RSTR + ((lane >> 3) & 1) * 16;

    float acc[2][8][4] = {};

    const int chunks = K >> 6;
    for (int c = 0; c < chunks; c++) {
        size_t koff = (size_t)c * 64;
        #pragma unroll
        for (int i = 0; i < 4; i++) {
            int u = tid + i * 256;
            int row = u >> 3, seg = u & 7;
            uint32_t d = (uint32_t)row * RSTR + seg * 16;
            *(uint4*)(smem + SA_HI + d) = *((const uint4*)(Ah + (size_t)(m0+row)*K + koff) + seg);
            *(uint4*)(smem + SA_LO + d) = *((const uint4*)(Al + (size_t)(m0+row)*K + koff) + seg);
            *(uint4*)(smem + SB_HI + d) = *((const uint4*)(Bh + (size_t)(n0+row)*K + koff) + seg);
            *(uint4*)(smem + SB_LO + d) = *((const uint4*)(Bl + (size_t)(n0+row)*K + koff) + seg);
        }
        __syncthreads();

        #pragma unroll
        for (int kk = 0; kk < 4; kk++) {
            uint32_t kb = kk * 32;
            uint32_t ah[2][4], al[2][4];
            ldsm4(ah[0], sb + SA_HI + aOff + kb);
            ldsm4(ah[1], sb + SA_HI + aOff + 16*RSTR + kb);
            ldsm4(al[0], sb + SA_LO + aOff + kb);
            ldsm4(al[1], sb + SA_LO + aOff + 16*RSTR + kb);
            uint32_t bh[4][4], bl[4][4];
            #pragma unroll
            for (int jp = 0; jp < 4; jp++) {
                ldsm4(bh[jp], sb + SB_HI + bOff + (uint32_t)jp*16*RSTR + kb);
                ldsm4(bl[jp], sb + SB_LO + bOff + (uint32_t)jp*16*RSTR + kb);
            }
            #pragma unroll
            for (int im = 0; im < 2; im++)
                #pragma unroll
                for (int jn = 0; jn < 8; jn++) {
                    const uint32_t* ph = &bh[jn >> 1][(jn & 1) * 2];
                    const uint32_t* pl = &bl[jn >> 1][(jn & 1) * 2];
                    mma_bf16(acc[im][jn], ah[im], ph);
                    mma_bf16(acc[im][jn], ah[im], pl);
                    mma_bf16(acc[im][jn], al[im], ph);
                }
        }
        __syncthreads();
    }

    int r = lane >> 2, cc = (lane & 3) * 2;
    #pragma unroll
    for (int im = 0; im < 2; im++) {
        int rg0 = m0 + wm * 32 + im * 16 + r;
        #pragma unroll
        for (int jn = 0; jn < 8; jn++) {
            int col = n0 + wn * 64 + jn * 8 + cc;
            float2 bv = *(const float2*)(bias + col);
            float v0 = (acc[im][jn][0] + bv.x) * scale;
            float v1 = (acc[im][jn][1] + bv.y) * scale;
            float v2 = (acc[im][jn][2] + bv.x) * scale;
            float v3 = (acc[im][jn][3] + bv.y) * scale;
            if (RELU) {
                v0 = fmaxf(v0, 0.f); v1 = fmaxf(v1, 0.f);
                v2 = fmaxf(v2, 0.f); v3 = fmaxf(v3, 0.f);
            }
            size_t o0 = (size_t)rg0 * N + col;
            size_t o1 = (size_t)(rg0 + 8) * N + col;
            if (RES) {
                float2 r0 = *(const float2*)(res + o0);
                float2 r1 = *(const float2*)(res + o1);
                v0 += r0.x; v1 += r0.y; v2 += r1.x; v3 += r1.y;
            }
            if (OUTM == 0) {
                *(float2*)(Cf + o0) = make_float2(v0, v1);
                *(float2*)(Cf + o1) = make_float2(v2, v3);
            } else if (OUTM == 1) {
                __nv_bfloat16 h0,l0,h1,l1,h2,l2,h3,l3;
                split_bf16(v0, h0, l0); split_bf16(v1, h1, l1);
                split_bf16(v2, h2, l2); split_bf16(v3, h3, l3);
                *(__nv_bfloat162*)(Ch + o0) = __halves2bfloat162(h0, h1);
                *(__nv_bfloat162*)(Ch + o1) = __halves2bfloat162(h2, h3);
                *(__nv_bfloat162*)(Cl + o0) = __halves2bfloat162(l0, l1);
                *(__nv_bfloat162*)(Cl + o1) = __halves2bfloat162(l2, l3);
            } else {
                *(__half2*)(Cs + o0) = __floats2half2_rn(v0, v1);
                *(__half2*)(Cs + o1) = __floats2half2_rn(v2, v3);
            }
        }
    }
}

// ========== rel = q @ Er^T, band tiles only, fp16 single (K = 64) ===========
#define REL_SMEM (2*ASZ)

__global__ __launch_bounds__(256)
void rel_mma(
    const __half* __restrict__ Qf, const __half* __restrict__ Ef,
    float* __restrict__ out)
{
    int m0 = blockIdx.y * 128, n0 = blockIdx.x * 128;
    if (m0 + n0 + 255 < SS - 1) return;   // tile never read by skew gather
    int bh = blockIdx.z;
    int b = bh >> 4, h = bh & 15;

    extern __shared__ char smem[];
    uint32_t sb = smem_u32(smem);
    int tid = threadIdx.x;
    int lane = tid & 31, wid = tid >> 5;
    int wm = wid & 3, wn = wid >> 2;

    const __half* Qp = Qf + ((size_t)b * SS) * DD + h * DH;

    #pragma unroll
    for (int i = 0; i < 4; i++) {
        int u = tid + i * 256;
        int row = u >> 3, seg = u & 7;
        uint32_t d = (uint32_t)row * RSTR + seg * 16;
        if (i < 2) { // A: 128 rows x 8 segs = 1024 slots -> i=0..3 covers; split A/B
            *(uint4*)(smem + 0   + d) = *((const uint4*)(Qp + (size_t)(m0+row)*DD) + seg);
            *(uint4*)(smem + ASZ + d) = *((const uint4*)(Ef + (size_t)(n0+row)*DH) + seg);
        } else {
            *(uint4*)(smem + 0   + d) = *((const uint4*)(Qp + (size_t)(m0+row)*DD) + seg);
            *(uint4*)(smem + ASZ + d) = *((const uint4*)(Ef + (size_t)(n0+row)*DH) + seg);
        }
    }
    __syncthreads();

    int aRow = wm * 32 + ((lane >> 3) & 1) * 8 + (lane & 7);
    uint32_t aOff = (uint32_t)aRow * RSTR + ((lane >> 4) & 1) * 16;
    int bRow = wn * 64 + ((lane >> 4) & 1) * 8 + (lane & 7);
    uint32_t bOff = (uint32_t)bRow * RSTR + ((lane >> 3) & 1) * 16;

    float acc[2][8][4] = {};
    #pragma unroll
    for (int kk = 0; kk < 4; kk++) {
        uint32_t kb = kk * 32;
        uint32_t ah[2][4];
        ldsm4(ah[0], sb + 0 + aOff + kb);
        ldsm4(ah[1], sb + 0 + aOff + 16*RSTR + kb);
        uint32_t bhf[4][4];
        #pragma unroll
        for (int jp = 0; jp < 4; jp++)
            ldsm4(bhf[jp], sb + ASZ + bOff + (uint32_t)jp*16*RSTR + kb);
        #pragma unroll
        for (int im = 0; im < 2; im++)
            #pragma unroll
            for (int jn = 0; jn < 8; jn++)
                mma_f16(acc[im][jn], ah[im], &bhf[jn >> 1][(jn & 1) * 2]);
    }

    float* ob = out + (size_t)bh * SS * SS;
    int r = lane >> 2, cc = (lane & 3) * 2;
    #pragma unroll
    for (int im = 0; im < 2; im++) {
        int rg0 = m0 + wm * 32 + im * 16 + r;
        #pragma unroll
        for (int jn = 0; jn < 8; jn++) {
            int col = n0 + wn * 64 + jn * 8 + cc;
            *(float2*)(ob + (size_t)rg0 * SS + col)      = make_float2(acc[im][jn][0], acc[im][jn][1]);
            *(float2*)(ob + (size_t)(rg0+8) * SS + col)  = make_float2(acc[im][jn][2], acc[im][jn][3]);
        }
    }
}

// ========== flash attention, fp16 single-product ============================
// CTA: one (b,h) and 64 q-rows, 128 threads (4 warps x 16 rows).
// smem 46080 B -> high occupancy.
#define FL_Q  0
#define FL_K  QSZ
#define FL_V  (QSZ + ASZ)
#define FL_SMEM (QSZ + 2*ASZ)    // 46080 B

__global__ __launch_bounds__(128)
void flash_mma(
    const __half* __restrict__ Qf, const __half* __restrict__ Kf,
    const __half* __restrict__ Vf, const float* __restrict__ REL,
    __nv_bfloat16* __restrict__ Oh, __nv_bfloat16* __restrict__ Ol)
{
    extern __shared__ char smem[];
    uint32_t sb = smem_u32(smem);
    int tid = threadIdx.x;
    int lane = tid & 31, w = tid >> 5;     // 4 warps
    int s0 = blockIdx.x * 64;
    int bh = blockIdx.y;
    int b = bh >> 4, h = bh & 15;

    const __half* qb = Qf + ((size_t)b * SS) * DD + h * DH;
    const __half* kb = Kf + ((size_t)b * SS) * DD + h * DH;
    const __half* vb = Vf + ((size_t)b * SS) * DD + h * DH;

    // stage Q (64 rows, persistent in smem)
    #pragma unroll
    for (int i = 0; i < 4; i++) {
        int u = tid + i * 128;
        int row = u >> 3, seg = u & 7;
        uint32_t d = (uint32_t)row * RSTR + seg * 16;
        *(uint4*)(smem + FL_Q + d) = *((const uint4*)(qb + (size_t)(s0+row)*DD) + seg);
    }

    int g = lane >> 2, qd = lane & 3;
    int sA = s0 + w * 16 + g;
    int sB = sA + 8;
    const float* rpA = REL + ((size_t)bh * SS + sA) * SS + (SS - 1 - sA);
    const float* rpB = REL + ((size_t)bh * SS + sB) * SS + (SS - 1 - sB);

    uint32_t aOff = (uint32_t)(w*16 + ((lane>>3)&1)*8 + (lane&7)) * RSTR + ((lane>>4)&1)*16;
    uint32_t bOff = (uint32_t)(((lane>>4)&1)*8 + (lane&7)) * RSTR + ((lane>>3)&1)*16;
    uint32_t vKr = ((lane>>3)&1)*8 + (lane&7);
    uint32_t vCb = ((lane>>4)&1)*16;

    float oacc[8][4] = {};
    float mA = -1e30f, mB = -1e30f, lA = 0.f, lB = 0.f;

    for (int c = 0; c < SS/128; c++) {
        int t0 = c * 128;
        __syncthreads();    // protect K/V smem reuse (and Q store on c==0)
        #pragma unroll
        for (int i = 0; i < 8; i++) {
            int u = tid + i * 128;
            int row = u >> 3, seg = u & 7;
            uint32_t d = (uint32_t)row * RSTR + seg * 16;
            *(uint4*)(smem + FL_K + d) = *((const uint4*)(kb + (size_t)(t0+row)*DD) + seg);
            *(uint4*)(smem + FL_V + d) = *((const uint4*)(vb + (size_t)(t0+row)*DD) + seg);
        }
        __syncthreads();

        // S = q @ k^T (fp16 single), 16 n-tiles of 8 cols
        float sacc[16][4] = {};
        #pragma unroll
        for (int kk = 0; kk < 4; kk++) {
            uint32_t kbo = kk * 32;
            uint32_t ah[4];
            ldsm4(ah, sb + FL_Q + aOff + kbo);
            #pragma unroll
            for (int jp = 0; jp < 8; jp++) {
                uint32_t bhf[4];
                ldsm4(bhf, sb + FL_K + bOff + (uint32_t)jp*16*RSTR + kbo);
                mma_f16(sacc[jp*2],   ah, &bhf[0]);
                mma_f16(sacc[jp*2+1], ah, &bhf[2]);
            }
        }

        // skew add: sacc[jn][0,1] row sA, [2,3] row sB, cols t0+8jn+2qd(+1)
        if (t0 <= sA) {
            #pragma unroll
            for (int jn = 0; jn < 16; jn++) {
                int t = t0 + jn * 8 + qd * 2;
                if (t     <= sA) sacc[jn][0] += __ldg(rpA + t);
                if (t + 1 <= sA) sacc[jn][1] += __ldg(rpA + t + 1);
            }
        }
        if (t0 <= sB) {
            #pragma unroll
            for (int jn = 0; jn < 16; jn++) {
                int t = t0 + jn * 8 + qd * 2;
                if (t     <= sB) sacc[jn][2] += __ldg(rpB + t);
                if (t + 1 <= sB) sacc[jn][3] += __ldg(rpB + t + 1);
            }
        }

        // online softmax
        float cmA = -1e30f, cmB = -1e30f;
        #pragma unroll
        for (int jn = 0; jn < 16; jn++) {
            cmA = fmaxf(cmA, fmaxf(sacc[jn][0], sacc[jn][1]));
            cmB = fmaxf(cmB, fmaxf(sacc[jn][2], sacc[jn][3]));
        }
        cmA = fmaxf(cmA, __shfl_xor_sync(0xFFFFFFFF, cmA, 1));
        cmA = fmaxf(cmA, __shfl_xor_sync(0xFFFFFFFF, cmA, 2));
        cmB = fmaxf(cmB, __shfl_xor_sync(0xFFFFFFFF, cmB, 1));
        cmB = fmaxf(cmB, __shfl_xor_sync(0xFFFFFFFF, cmB, 2));
        float mnA = fmaxf(mA, cmA), mnB = fmaxf(mB, cmB);
        float alA = __expf(mA - mnA), alB = __expf(mB - mnB);
        mA = mnA; mB = mnB;

        float suA = 0.f, suB = 0.f;
        #pragma unroll
        for (int jn = 0; jn < 16; jn++) {
            sacc[jn][0] = __expf(sacc[jn][0] - mnA);
            sacc[jn][1] = __expf(sacc[jn][1] - mnA);
            sacc[jn][2] = __expf(sacc[jn][2] - mnB);
            sacc[jn][3] = __expf(sacc[jn][3] - mnB);
            suA += sacc[jn][0] + sacc[jn][1];
            suB += sacc[jn][2] + sacc[jn][3];
        }
        suA += __shfl_xor_sync(0xFFFFFFFF, suA, 1);
        suA += __shfl_xor_sync(0xFFFFFFFF, suA, 2);
        suB += __shfl_xor_sync(0xFFFFFFFF, suB, 1);
        suB += __shfl_xor_sync(0xFFFFFFFF, suB, 2);
        lA = lA * alA + suA;
        lB = lB * alB + suB;

        // rescale O
        #pragma unroll
        for (int jn = 0; jn < 8; jn++) {
            oacc[jn][0] *= alA; oacc[jn][1] *= alA;
            oacc[jn][2] *= alB; oacc[jn][3] *= alB;
        }

        // O += P @ V (fp16 single), 8 k-steps of 16
        #pragma unroll
        for (int k2 = 0; k2 < 8; k2++) {
            uint32_t pa[4];
            pa[0] = pack_f16(sacc[2*k2][0],   sacc[2*k2][1]);
            pa[1] = pack_f16(sacc[2*k2][2],   sacc[2*k2][3]);
            pa[2] = pack_f16(sacc[2*k2+1][0], sacc[2*k2+1][1]);
            pa[3] = pack_f16(sacc[2*k2+1][2], sacc[2*k2+1][3]);
            uint32_t vRowOff = (uint32_t)(k2 * 16 + vKr) * RSTR;
            #pragma unroll
            for (int jp = 0; jp < 4; jp++) {
                uint32_t vh4[4];
                ldsm4t(vh4, sb + FL_V + vRowOff + vCb + jp * 32);
                mma_f16(oacc[jp*2],   pa, &vh4[0]);
                mma_f16(oacc[jp*2+1], pa, &vh4[2]);
            }
        }
    }

    // epilogue: normalize + split store (bf16 hi/lo for Wo GEMM)
    float invA = 1.f / lA, invB = 1.f / lB;
    #pragma unroll
    for (int jn = 0; jn < 8; jn++) {
        int col = h * DH + jn * 8 + qd * 2;
        size_t oA = ((size_t)b * SS + sA) * DD + col;
        size_t oB = ((size_t)b * SS + sB) * DD + col;
        __nv_bfloat16 h0,l0,h1,l1;
        split_bf16(oacc[jn][0] * invA, h0, l0);
        split_bf16(oacc[jn][1] * invA, h1, l1);
        *(__nv_bfloat162*)(Oh + oA) = __halves2bfloat162(h0, h1);
        *(__nv_bfloat162*)(Ol + oA) = __halves2bfloat162(l0, l1);
        split_bf16(oacc[jn][2] * invB, h0, l0);
        split_bf16(oacc[jn][3] * invB, h1, l1);
        *(__nv_bfloat162*)(Oh + oB) = __halves2bfloat162(h0, h1);
        *(__nv_bfloat162*)(Ol + oB) = __halves2bfloat162(l0, l1);
    }
}

// ---------------- launch ----------------------------------------------------
extern "C" void kernel_launch(void* const* d_in, const int* in_sizes, int n_in,
                              void* d_out, int out_size)
{
    (void)in_sizes; (void)n_in; (void)out_size;
    const float* x   = (const float*)d_in[0];
    const float* Wq  = (const float*)d_in[1];
    const float* bq  = (const float*)d_in[2];
    const float* Wk  = (const float*)d_in[3];
    const float* bk  = (const float*)d_in[4];
    const float* Wv  = (const float*)d_in[5];
    const float* bv  = (const float*)d_in[6];
    const float* Wo  = (const float*)d_in[7];
    const float* bo  = (const float*)d_in[8];
    const float* Er  = (const float*)d_in[9];
    const float* W1  = (const float*)d_in[10];
    const float* b1  = (const float*)d_in[11];
    const float* W2  = (const float*)d_in[12];
    const float* b2  = (const float*)d_in[13];
    const float* g1  = (const float*)d_in[14];
    const float* be1 = (const float*)d_in[15];
    const float* g2  = (const float*)d_in[16];
    const float* be2 = (const float*)d_in[17];
    float* y = (float*)d_out;

    float *px1, *prel, *px2, *px3;
    cudaGetSymbolAddress((void**)&px1,  g_x1);
    cudaGetSymbolAddress((void**)&prel, g_rel);
    cudaGetSymbolAddress((void**)&px2,  g_x2);
    cudaGetSymbolAddress((void**)&px3,  g_x3);

    __nv_bfloat16 *x1h,*x1l,*x3h,*x3l,*avh,*avl,*h1h,*h1l;
    __half *qf,*kf,*vf,*erf;
    __nv_bfloat16 *wqh,*wql,*wkh,*wkl,*wvh,*wvl,*woh,*wol,*w1h,*w1l,*w2h,*w2l;
    cudaGetSymbolAddress((void**)&x1h, g_x1h); cudaGetSymbolAddress((void**)&x1l, g_x1l);
    cudaGetSymbolAddress((void**)&x3h, g_x3h); cudaGetSymbolAddress((void**)&x3l, g_x3l);
    cudaGetSymbolAddress((void**)&qf,  g_qf);
    cudaGetSymbolAddress((void**)&kf,  g_kf);
    cudaGetSymbolAddress((void**)&vf,  g_vf);
    cudaGetSymbolAddress((void**)&avh, g_avh); cudaGetSymbolAddress((void**)&avl, g_avl);
    cudaGetSymbolAddress((void**)&h1h, g_h1h); cudaGetSymbolAddress((void**)&h1l, g_h1l);
    cudaGetSymbolAddress((void**)&erf, g_erf);
    cudaGetSymbolAddress((void**)&wqh, g_wqh); cudaGetSymbolAddress((void**)&wql, g_wql);
    cudaGetSymbolAddress((void**)&wkh, g_wkh); cudaGetSymbolAddress((void**)&wkl, g_wkl);
    cudaGetSymbolAddress((void**)&wvh, g_wvh); cudaGetSymbolAddress((void**)&wvl, g_wvl);
    cudaGetSymbolAddress((void**)&woh, g_woh); cudaGetSymbolAddress((void**)&wol, g_wol);
    cudaGetSymbolAddress((void**)&w1h, g_w1h); cudaGetSymbolAddress((void**)&w1l, g_w1l);
    cudaGetSymbolAddress((void**)&w2h, g_w2h); cudaGetSymbolAddress((void**)&w2l, g_w2l);

    cudaFuncSetAttribute(gemm_mma<0,false,true>,  cudaFuncAttributeMaxDynamicSharedMemorySize, GEMM_SMEM);
    cudaFuncSetAttribute(gemm_mma<1,false,false>, cudaFuncAttributeMaxDynamicSharedMemorySize, GEMM_SMEM);
    cudaFuncSetAttribute(gemm_mma<1,true,false>,  cudaFuncAttributeMaxDynamicSharedMemorySize, GEMM_SMEM);
    cudaFuncSetAttribute(gemm_mma<2,false,false>, cudaFuncAttributeMaxDynamicSharedMemorySize, GEMM_SMEM);
    cudaFuncSetAttribute(rel_mma,   cudaFuncAttributeMaxDynamicSharedMemorySize, REL_SMEM);
    cudaFuncSetAttribute(flash_mma, cudaFuncAttributeMaxDynamicSharedMemorySize, FL_SMEM);

    // weight transpose + split
    convBT<<<dim3(DD/32, DD/32), 256>>>(Wq, wqh, wql, DD, DD);
    convBT<<<dim3(DD/32, DD/32), 256>>>(Wk, wkh, wkl, DD, DD);
    convBT<<<dim3(DD/32, DD/32), 256>>>(Wv, wvh, wvl, DD, DD);
    convBT<<<dim3(DD/32, DD/32), 256>>>(Wo, woh, wol, DD, DD);
    convBT<<<dim3(FF/32, DD/32), 256>>>(W1, w1h, w1l, DD, FF);
    convBT<<<dim3(DD/32, FF/32), 256>>>(W2, w2h, w2l, FF, DD);
    convEf<<<(SS*DH + 1023)/1024, 256>>>(Er, erf, SS*DH);

    // x1 = LN(x)
    ln_kernel<<<MM, 256>>>(x, g1, be1, px1, x1h, x1l);
    // q/k/v -> fp16 single
    gemm_mma<2,false,false><<<dim3(DD/128, MM/128), 256, GEMM_SMEM>>>(
        x1h, x1l, wqh, wql, bq, nullptr, nullptr, nullptr, nullptr, qf, DD, DD, 0.125f);
    gemm_mma<2,false,false><<<dim3(DD/128, MM/128), 256, GEMM_SMEM>>>(
        x1h, x1l, wkh, wkl, bk, nullptr, nullptr, nullptr, nullptr, kf, DD, DD, 1.f);
    gemm_mma<2,false,false><<<dim3(DD/128, MM/128), 256, GEMM_SMEM>>>(
        x1h, x1l, wvh, wvl, bv, nullptr, nullptr, nullptr, nullptr, vf, DD, DD, 1.f);
    // rel = q@Er^T (band tiles, fp16 single)
    rel_mma<<<dim3(SS/128, SS/128, BB*HH), 256, REL_SMEM>>>(qf, erf, prel);
    // fused attention (fp16 single-product)
    flash_mma<<<dim3(SS/64, BB*HH), 128, FL_SMEM>>>(qf, kf, vf, prel, avh, avl);
    // x2 = x1 + av@Wo + bo
    gemm_mma<0,false,true><<<dim3(DD/128, MM/128), 256, GEMM_SMEM>>>(
        avh, avl, woh, wol, bo, px1, px2, nullptr, nullptr, nullptr, DD, DD, 1.f);
    // x3 = LN(x2)
    ln_kernel<<<MM, 256>>>(px2, g2, be2, px3, x3h, x3l);
    // h1 = relu(x3@W1+b1)
    gemm_mma<1,true,false><<<dim3(FF/128, MM/128), 256, GEMM_SMEM>>>(
        x3h, x3l, w1h, w1l, b1, nullptr, nullptr, h1h, h1l, nullptr, FF, DD, 1.f);
    // y = x3 + h1@W2 + b2
    gemm_mma<0,false,true><<<dim3(DD/128, MM/128), 256, GEMM_SMEM>>>(
        h1h, h1l, w2h, w2l, b2, px3, y, nullptr, nullptr, nullptr, DD, FF, 1.f);
}

// round 9
// speedup vs baseline: 1.6070x; 1.1995x over previous
#include <cuda_runtime.h>
#include <cuda_bf16.h>
#include <cuda_fp16.h>
#include <math.h>
#include <stdint.h>

#define BB 2
#define SS 2048
#define DD 1024
#define HH 16
#define DH 64
#define FF 4096
#define MM (BB*SS)   // 4096 rows

// ---------------- scratch (device globals; no allocation allowed) ----------
__device__ float g_x1 [MM*DD];
__device__ float g_rel[(size_t)BB*HH*SS*SS];   // q@Er^T (upper band tiles only)
__device__ float g_x2 [MM*DD];
__device__ float g_x3 [MM*DD];

__device__ __half g_x1h[MM*DD],  g_x1l[MM*DD];
__device__ __half g_x3h[MM*DD],  g_x3l[MM*DD];
__device__ __half g_qf [MM*DD];
__device__ __half g_kf [MM*DD];
__device__ __half g_vf [MM*DD];
__device__ __half g_avh[MM*DD],  g_avl[MM*DD];
__device__ __half g_h1h[(size_t)MM*FF], g_h1l[(size_t)MM*FF];
__device__ __half g_erf[SS*DH];
__device__ __half g_wq[DD*DD], g_wk[DD*DD], g_wv[DD*DD], g_wo[DD*DD];
__device__ __half g_w1[(size_t)DD*FF], g_w2[(size_t)DD*FF];

// ======================= helpers ============================================
__device__ __forceinline__ uint32_t smem_u32(const void* p) {
    uint32_t a;
    asm("{ .reg .u64 t; cvta.to.shared.u64 t, %1; cvt.u32.u64 %0, t; }"
        : "=r"(a) : "l"(p));
    return a;
}
__device__ __forceinline__ void ldsm4(uint32_t* r, uint32_t addr) {
    asm volatile("ldmatrix.sync.aligned.m8n8.x4.shared.b16 {%0,%1,%2,%3}, [%4];"
        : "=r"(r[0]), "=r"(r[1]), "=r"(r[2]), "=r"(r[3]) : "r"(addr));
}
__device__ __forceinline__ void ldsm4t(uint32_t* r, uint32_t addr) {
    asm volatile("ldmatrix.sync.aligned.m8n8.x4.trans.shared.b16 {%0,%1,%2,%3}, [%4];"
        : "=r"(r[0]), "=r"(r[1]), "=r"(r[2]), "=r"(r[3]) : "r"(addr));
}
__device__ __forceinline__ void mma_f16(float* c, const uint32_t* a, const uint32_t* b) {
    asm volatile("mma.sync.aligned.m16n8k16.row.col.f32.f16.f16.f32 "
        "{%0,%1,%2,%3}, {%4,%5,%6,%7}, {%8,%9}, {%0,%1,%2,%3};"
        : "+f"(c[0]), "+f"(c[1]), "+f"(c[2]), "+f"(c[3])
        : "r"(a[0]), "r"(a[1]), "r"(a[2]), "r"(a[3]), "r"(b[0]), "r"(b[1]));
}
__device__ __forceinline__ void split_f16(float v, __half& h, __half& l) {
    h = __float2half_rn(v);
    l = __float2half_rn(v - __half2float(h));
}
__device__ __forceinline__ uint32_t pack_f16(float x, float y) {
    __half2 h = __floats2half2_rn(x, y);
    return *(uint32_t*)&h;
}

#define RSTR 144
#define ASZ (128 * RSTR)          // 18432 B per 128x64 16-bit array
#define QSZ (64 * RSTR)           // 9216 B per 64x64 16-bit array

// ================== weight transpose + fp16: [K][N] -> [N][K] ===============
__global__ __launch_bounds__(256) void convBTf(
    const float* __restrict__ W, __half* __restrict__ T, int K, int N)
{
    __shared__ float ts[32][33];
    int n0 = blockIdx.x * 32, k0 = blockIdx.y * 32;
    int tx = threadIdx.x & 31, ty = threadIdx.x >> 5;
    #pragma unroll
    for (int i = 0; i < 4; i++)
        ts[ty + 8*i][tx] = W[(size_t)(k0 + ty + 8*i) * N + n0 + tx];
    __syncthreads();
    #pragma unroll
    for (int i = 0; i < 4; i++) {
        int n = ty + 8*i;
        T[(size_t)(n0 + n) * K + k0 + tx] = __float2half_rn(ts[tx][n]);
    }
}

// -------- elementwise f16 convert (Er) ---------------------------------------
__global__ __launch_bounds__(256) void convEf(
    const float* __restrict__ X, __half* __restrict__ Xf, int n)
{
    int i = blockIdx.x * 1024 + threadIdx.x * 4;
    if (i >= n) return;
    float4 v = *(const float4*)(X + i);
    *(__half2*)(Xf + i)     = __floats2half2_rn(v.x, v.y);
    *(__half2*)(Xf + i + 2) = __floats2half2_rn(v.z, v.w);
}

// ---------------- LayerNorm: fp32 out + fp16 hi/lo split --------------------
__global__ __launch_bounds__(256) void ln_kernel(
    const float* __restrict__ X, const float* __restrict__ g,
    const float* __restrict__ be, float* __restrict__ Y,
    __half* __restrict__ Yh, __half* __restrict__ Yl)
{
    int row = blockIdx.x;
    size_t base = (size_t)row * DD;
    int tid = threadIdx.x;
    float4 v = *(const float4*)(X + base + tid * 4);
    float s = v.x + v.y + v.z + v.w;
    float q = v.x*v.x + v.y*v.y + v.z*v.z + v.w*v.w;

    __shared__ float rs[32], rq[32];
    #pragma unroll
    for (int o = 16; o > 0; o >>= 1) {
        s += __shfl_xor_sync(0xFFFFFFFF, s, o);
        q += __shfl_xor_sync(0xFFFFFFFF, q, o);
    }
    int lane = tid & 31, w = tid >> 5;
    if (lane == 0) { rs[w] = s; rq[w] = q; }
    __syncthreads();
    if (w == 0) {
        s = (lane < 8) ? rs[lane] : 0.f;
        q = (lane < 8) ? rq[lane] : 0.f;
        #pragma unroll
        for (int o = 4; o > 0; o >>= 1) {
            s += __shfl_xor_sync(0xFFFFFFFF, s, o);
            q += __shfl_xor_sync(0xFFFFFFFF, q, o);
        }
        if (lane == 0) { rs[0] = s; rq[0] = q; }
    }
    __syncthreads();
    float mean = rs[0] * (1.f / DD);
    float var  = rq[0] * (1.f / DD) - mean * mean;
    float rstd = rsqrtf(var + 1e-5f);

    float4 gv = *(const float4*)(g  + tid * 4);
    float4 bv = *(const float4*)(be + tid * 4);
    float4 o4;
    o4.x = (v.x - mean) * rstd * gv.x + bv.x;
    o4.y = (v.y - mean) * rstd * gv.y + bv.y;
    o4.z = (v.z - mean) * rstd * gv.z + bv.z;
    o4.w = (v.w - mean) * rstd * gv.w + bv.w;
    *(float4*)(Y + base + tid * 4) = o4;

    __half h0,l0,h1,l1,h2,l2,h3,l3;
    split_f16(o4.x, h0, l0); split_f16(o4.y, h1, l1);
    split_f16(o4.z, h2, l2); split_f16(o4.w, h3, l3);
    *(__half2*)(Yh + base + tid*4)     = __halves2half2(h0, h1);
    *(__half2*)(Yh + base + tid*4 + 2) = __halves2half2(h2, h3);
    *(__half2*)(Yl + base + tid*4)     = __halves2half2(l0, l1);
    *(__half2*)(Yl + base + tid*4 + 2) = __halves2half2(l2, l3);
}

// ====== mma.sync fp16 2-term GEMM: C = epi((Ah+Al)@B^T + bias) ==============
// A (hi/lo): [M][K] fp16 row-major.  B: [N][K] fp16 row-major (single).
// OUTM: 0 = f32, 1 = f16 hi/lo pair, 2 = f16 single
#define SA_HI 0
#define SA_LO ASZ
#define SB    (2*ASZ)
#define GEMM_SMEM (3*ASZ)         // 55296 B

template<int OUTM, bool RELU, bool RES>
__global__ __launch_bounds__(256)
void gemm_mma(
    const __half* __restrict__ Ah, const __half* __restrict__ Al,
    const __half* __restrict__ Bm,
    const float* __restrict__ bias, const float* __restrict__ res,
    float* __restrict__ Cf, __half* __restrict__ Ch,
    __half* __restrict__ Cl, __half* __restrict__ Cs,
    int N, int K, float scale)
{
    extern __shared__ char smem[];
    uint32_t sb = smem_u32(smem);
    int tid = threadIdx.x;
    int lane = tid & 31, wid = tid >> 5;
    int wm = wid & 3, wn = wid >> 2;
    int m0 = blockIdx.y * 128, n0 = blockIdx.x * 128;

    int aRow = wm * 32 + ((lane >> 3) & 1) * 8 + (lane & 7);
    uint32_t aOff = (uint32_t)aRow * RSTR + ((lane >> 4) & 1) * 16;
    int bRow = wn * 64 + ((lane >> 4) & 1) * 8 + (lane & 7);
    uint32_t bOff = (uint32_t)bRow * RSTR + ((lane >> 3) & 1) * 16;

    float acc[2][8][4] = {};

    const int chunks = K >> 6;
    for (int c = 0; c < chunks; c++) {
        size_t koff = (size_t)c * 64;
        #pragma unroll
        for (int i = 0; i < 4; i++) {
            int u = tid + i * 256;
            int row = u >> 3, seg = u & 7;
            uint32_t d = (uint32_t)row * RSTR + seg * 16;
            *(uint4*)(smem + SA_HI + d) = *((const uint4*)(Ah + (size_t)(m0+row)*K + koff) + seg);
            *(uint4*)(smem + SA_LO + d) = *((const uint4*)(Al + (size_t)(m0+row)*K + koff) + seg);
            *(uint4*)(smem + SB    + d) = *((const uint4*)(Bm + (size_t)(n0+row)*K + koff) + seg);
        }
        __syncthreads();

        #pragma unroll
        for (int kk = 0; kk < 4; kk++) {
            uint32_t kb = kk * 32;
            uint32_t ah[2][4], al[2][4];
            ldsm4(ah[0], sb + SA_HI + aOff + kb);
            ldsm4(ah[1], sb + SA_HI + aOff + 16*RSTR + kb);
            ldsm4(al[0], sb + SA_LO + aOff + kb);
            ldsm4(al[1], sb + SA_LO + aOff + 16*RSTR + kb);
            uint32_t bh[4][4];
            #pragma unroll
            for (int jp = 0; jp < 4; jp++)
                ldsm4(bh[jp], sb + SB + bOff + (uint32_t)jp*16*RSTR + kb);
            #pragma unroll
            for (int im = 0; im < 2; im++)
                #pragma unroll
                for (int jn = 0; jn < 8; jn++) {
                    const uint32_t* ph = &bh[jn >> 1][(jn & 1) * 2];
                    mma_f16(acc[im][jn], ah[im], ph);
                    mma_f16(acc[im][jn], al[im], ph);
                }
        }
        __syncthreads();
    }

    int r = lane >> 2, cc = (lane & 3) * 2;
    #pragma unroll
    for (int im = 0; im < 2; im++) {
        int rg0 = m0 + wm * 32 + im * 16 + r;
        #pragma unroll
        for (int jn = 0; jn < 8; jn++) {
            int col = n0 + wn * 64 + jn * 8 + cc;
            float2 bv = *(const float2*)(bias + col);
            float v0 = (acc[im][jn][0] + bv.x) * scale;
            float v1 = (acc[im][jn][1] + bv.y) * scale;
            float v2 = (acc[im][jn][2] + bv.x) * scale;
            float v3 = (acc[im][jn][3] + bv.y) * scale;
            if (RELU) {
                v0 = fmaxf(v0, 0.f); v1 = fmaxf(v1, 0.f);
                v2 = fmaxf(v2, 0.f); v3 = fmaxf(v3, 0.f);
            }
            size_t o0 = (size_t)rg0 * N + col;
            size_t o1 = (size_t)(rg0 + 8) * N + col;
            if (RES) {
                float2 r0 = *(const float2*)(res + o0);
                float2 r1 = *(const float2*)(res + o1);
                v0 += r0.x; v1 += r0.y; v2 += r1.x; v3 += r1.y;
            }
            if (OUTM == 0) {
                *(float2*)(Cf + o0) = make_float2(v0, v1);
                *(float2*)(Cf + o1) = make_float2(v2, v3);
            } else if (OUTM == 1) {
                __half h0,l0,h1,l1,h2,l2,h3,l3;
                split_f16(v0, h0, l0); split_f16(v1, h1, l1);
                split_f16(v2, h2, l2); split_f16(v3, h3, l3);
                *(__half2*)(Ch + o0) = __halves2half2(h0, h1);
                *(__half2*)(Ch + o1) = __halves2half2(h2, h3);
                *(__half2*)(Cl + o0) = __halves2half2(l0, l1);
                *(__half2*)(Cl + o1) = __halves2half2(l2, l3);
            } else {
                *(__half2*)(Cs + o0) = __floats2half2_rn(v0, v1);
                *(__half2*)(Cs + o1) = __floats2half2_rn(v2, v3);
            }
        }
    }
}

// ========== rel = q @ Er^T, band tiles only, fp16 single (K = 64) ===========
#define REL_SMEM (2*ASZ)

__global__ __launch_bounds__(256)
void rel_mma(
    const __half* __restrict__ Qf, const __half* __restrict__ Ef,
    float* __restrict__ out)
{
    int m0 = blockIdx.y * 128, n0 = blockIdx.x * 128;
    if (m0 + n0 + 255 < SS - 1) return;   // tile never read by skew gather
    int bh = blockIdx.z;
    int b = bh >> 4, h = bh & 15;

    extern __shared__ char smem[];
    uint32_t sb = smem_u32(smem);
    int tid = threadIdx.x;
    int lane = tid & 31, wid = tid >> 5;
    int wm = wid & 3, wn = wid >> 2;

    const __half* Qp = Qf + ((size_t)b * SS) * DD + h * DH;

    #pragma unroll
    for (int i = 0; i < 4; i++) {
        int u = tid + i * 256;
        int row = u >> 3, seg = u & 7;
        uint32_t d = (uint32_t)row * RSTR + seg * 16;
        *(uint4*)(smem + 0   + d) = *((const uint4*)(Qp + (size_t)(m0+row)*DD) + seg);
        *(uint4*)(smem + ASZ + d) = *((const uint4*)(Ef + (size_t)(n0+row)*DH) + seg);
    }
    __syncthreads();

    int aRow = wm * 32 + ((lane >> 3) & 1) * 8 + (lane & 7);
    uint32_t aOff = (uint32_t)aRow * RSTR + ((lane >> 4) & 1) * 16;
    int bRow = wn * 64 + ((lane >> 4) & 1) * 8 + (lane & 7);
    uint32_t bOff = (uint32_t)bRow * RSTR + ((lane >> 3) & 1) * 16;

    float acc[2][8][4] = {};
    #pragma unroll
    for (int kk = 0; kk < 4; kk++) {
        uint32_t kb = kk * 32;
        uint32_t ah[2][4];
        ldsm4(ah[0], sb + 0 + aOff + kb);
        ldsm4(ah[1], sb + 0 + aOff + 16*RSTR + kb);
        uint32_t bhf[4][4];
        #pragma unroll
        for (int jp = 0; jp < 4; jp++)
            ldsm4(bhf[jp], sb + ASZ + bOff + (uint32_t)jp*16*RSTR + kb);
        #pragma unroll
        for (int im = 0; im < 2; im++)
            #pragma unroll
            for (int jn = 0; jn < 8; jn++)
                mma_f16(acc[im][jn], ah[im], &bhf[jn >> 1][(jn & 1) * 2]);
    }

    float* ob = out + (size_t)bh * SS * SS;
    int r = lane >> 2, cc = (lane & 3) * 2;
    #pragma unroll
    for (int im = 0; im < 2; im++) {
        int rg0 = m0 + wm * 32 + im * 16 + r;
        #pragma unroll
        for (int jn = 0; jn < 8; jn++) {
            int col = n0 + wn * 64 + jn * 8 + cc;
            *(float2*)(ob + (size_t)rg0 * SS + col)      = make_float2(acc[im][jn][0], acc[im][jn][1]);
            *(float2*)(ob + (size_t)(rg0+8) * SS + col)  = make_float2(acc[im][jn][2], acc[im][jn][3]);
        }
    }
}

// ========== flash attention, fp16 single-product ============================
// CTA: one (b,h) and 64 q-rows, 128 threads (4 warps x 16 rows).
#define FL_Q  0
#define FL_K  QSZ
#define FL_V  (QSZ + ASZ)
#define FL_SMEM (QSZ + 2*ASZ)    // 46080 B

__global__ __launch_bounds__(128)
void flash_mma(
    const __half* __restrict__ Qf, const __half* __restrict__ Kf,
    const __half* __restrict__ Vf, const float* __restrict__ REL,
    __half* __restrict__ Oh, __half* __restrict__ Ol)
{
    extern __shared__ char smem[];
    uint32_t sb = smem_u32(smem);
    int tid = threadIdx.x;
    int lane = tid & 31, w = tid >> 5;     // 4 warps
    int s0 = blockIdx.x * 64;
    int bh = blockIdx.y;
    int b = bh >> 4, h = bh & 15;

    const __half* qb = Qf + ((size_t)b * SS) * DD + h * DH;
    const __half* kb = Kf + ((size_t)b * SS) * DD + h * DH;
    const __half* vb = Vf + ((size_t)b * SS) * DD + h * DH;

    // stage Q (64 rows, persistent in smem)
    #pragma unroll
    for (int i = 0; i < 4; i++) {
        int u = tid + i * 128;
        int row = u >> 3, seg = u & 7;
        uint32_t d = (uint32_t)row * RSTR + seg * 16;
        *(uint4*)(smem + FL_Q + d) = *((const uint4*)(qb + (size_t)(s0+row)*DD) + seg);
    }

    int g = lane >> 2, qd = lane & 3;
    int sA = s0 + w * 16 + g;
    int sB = sA + 8;
    const float* rpA = REL + ((size_t)bh * SS + sA) * SS + (SS - 1 - sA);
    const float* rpB = REL + ((size_t)bh * SS + sB) * SS + (SS - 1 - sB);

    uint32_t aOff = (uint32_t)(w*16 + ((lane>>3)&1)*8 + (lane&7)) * RSTR + ((lane>>4)&1)*16;
    uint32_t bOff = (uint32_t)(((lane>>4)&1)*8 + (lane&7)) * RSTR + ((lane>>3)&1)*16;
    uint32_t vKr = ((lane>>3)&1)*8 + (lane&7);
    uint32_t vCb = ((lane>>4)&1)*16;

    float oacc[8][4] = {};
    float mA = -1e30f, mB = -1e30f, lA = 0.f, lB = 0.f;

    for (int c = 0; c < SS/128; c++) {
        int t0 = c * 128;
        __syncthreads();    // protect K/V smem reuse (and Q store on c==0)
        #pragma unroll
        for (int i = 0; i < 8; i++) {
            int u = tid + i * 128;
            int row = u >> 3, seg = u & 7;
            uint32_t d = (uint32_t)row * RSTR + seg * 16;
            *(uint4*)(smem + FL_K + d) = *((const uint4*)(kb + (size_t)(t0+row)*DD) + seg);
            *(uint4*)(smem + FL_V + d) = *((const uint4*)(vb + (size_t)(t0+row)*DD) + seg);
        }
        __syncthreads();

        // S = q @ k^T (fp16 single), 16 n-tiles of 8 cols
        float sacc[16][4] = {};
        #pragma unroll
        for (int kk = 0; kk < 4; kk++) {
            uint32_t kbo = kk * 32;
            uint32_t ah[4];
            ldsm4(ah, sb + FL_Q + aOff + kbo);
            #pragma unroll
            for (int jp = 0; jp < 8; jp++) {
                uint32_t bhf[4];
                ldsm4(bhf, sb + FL_K + bOff + (uint32_t)jp*16*RSTR + kbo);
                mma_f16(sacc[jp*2],   ah, &bhf[0]);
                mma_f16(sacc[jp*2+1], ah, &bhf[2]);
            }
        }

        // skew add: sacc[jn][0,1] row sA, [2,3] row sB, cols t0+8jn+2qd(+1)
        if (t0 <= sA) {
            #pragma unroll
            for (int jn = 0; jn < 16; jn++) {
                int t = t0 + jn * 8 + qd * 2;
                if (t     <= sA) sacc[jn][0] += __ldg(rpA + t);
                if (t + 1 <= sA) sacc[jn][1] += __ldg(rpA + t + 1);
            }
        }
        if (t0 <= sB) {
            #pragma unroll
            for (int jn = 0; jn < 16; jn++) {
                int t = t0 + jn * 8 + qd * 2;
                if (t     <= sB) sacc[jn][2] += __ldg(rpB + t);
                if (t + 1 <= sB) sacc[jn][3] += __ldg(rpB + t + 1);
            }
        }

        // online softmax
        float cmA = -1e30f, cmB = -1e30f;
        #pragma unroll
        for (int jn = 0; jn < 16; jn++) {
            cmA = fmaxf(cmA, fmaxf(sacc[jn][0], sacc[jn][1]));
            cmB = fmaxf(cmB, fmaxf(sacc[jn][2], sacc[jn][3]));
        }
        cmA = fmaxf(cmA, __shfl_xor_sync(0xFFFFFFFF, cmA, 1));
        cmA = fmaxf(cmA, __shfl_xor_sync(0xFFFFFFFF, cmA, 2));
        cmB = fmaxf(cmB, __shfl_xor_sync(0xFFFFFFFF, cmB, 1));
        cmB = fmaxf(cmB, __shfl_xor_sync(0xFFFFFFFF, cmB, 2));
        float mnA = fmaxf(mA, cmA), mnB = fmaxf(mB, cmB);
        float alA = __expf(mA - mnA), alB = __expf(mB - mnB);
        mA = mnA; mB = mnB;

        float suA = 0.f, suB = 0.f;
        #pragma unroll
        for (int jn = 0; jn < 16; jn++) {
            sacc[jn][0] = __expf(sacc[jn][0] - mnA);
            sacc[jn][1] = __expf(sacc[jn][1] - mnA);
            sacc[jn][2] = __expf(sacc[jn][2] - mnB);
            sacc[jn][3] = __expf(sacc[jn][3] - mnB);
            suA += sacc[jn][0] + sacc[jn][1];
            suB += sacc[jn][2] + sacc[jn][3];
        }
        suA += __shfl_xor_sync(0xFFFFFFFF, suA, 1);
        suA += __shfl_xor_sync(0xFFFFFFFF, suA, 2);
        suB += __shfl_xor_sync(0xFFFFFFFF, suB, 1);
        suB += __shfl_xor_sync(0xFFFFFFFF, suB, 2);
        lA = lA * alA + suA;
        lB = lB * alB + suB;

        // rescale O
        #pragma unroll
        for (int jn = 0; jn < 8; jn++) {
            oacc[jn][0] *= alA; oacc[jn][1] *= alA;
            oacc[jn][2] *= alB; oacc[jn][3] *= alB;
        }

        // O += P @ V (fp16 single), 8 k-steps of 16
        #pragma unroll
        for (int k2 = 0; k2 < 8; k2++) {
            uint32_t pa[4];
            pa[0] = pack_f16(sacc[2*k2][0],   sacc[2*k2][1]);
            pa[1] = pack_f16(sacc[2*k2][2],   sacc[2*k2][3]);
            pa[2] = pack_f16(sacc[2*k2+1][0], sacc[2*k2+1][1]);
            pa[3] = pack_f16(sacc[2*k2+1][2], sacc[2*k2+1][3]);
            uint32_t vRowOff = (uint32_t)(k2 * 16 + vKr) * RSTR;
            #pragma unroll
            for (int jp = 0; jp < 4; jp++) {
                uint32_t vh4[4];
                ldsm4t(vh4, sb + FL_V + vRowOff + vCb + jp * 32);
                mma_f16(oacc[jp*2],   pa, &vh4[0]);
                mma_f16(oacc[jp*2+1], pa, &vh4[2]);
            }
        }
    }

    // epilogue: normalize + fp16 hi/lo store (for Wo GEMM)
    float invA = 1.f / lA, invB = 1.f / lB;
    #pragma unroll
    for (int jn = 0; jn < 8; jn++) {
        int col = h * DH + jn * 8 + qd * 2;
        size_t oA = ((size_t)b * SS + sA) * DD + col;
        size_t oB = ((size_t)b * SS + sB) * DD + col;
        __half h0,l0,h1,l1;
        split_f16(oacc[jn][0] * invA, h0, l0);
        split_f16(oacc[jn][1] * invA, h1, l1);
        *(__half2*)(Oh + oA) = __halves2half2(h0, h1);
        *(__half2*)(Ol + oA) = __halves2half2(l0, l1);
        split_f16(oacc[jn][2] * invB, h0, l0);
        split_f16(oacc[jn][3] * invB, h1, l1);
        *(__half2*)(Oh + oB) = __halves2half2(h0, h1);
        *(__half2*)(Ol + oB) = __halves2half2(l0, l1);
    }
}

// ---------------- launch ----------------------------------------------------
extern "C" void kernel_launch(void* const* d_in, const int* in_sizes, int n_in,
                              void* d_out, int out_size)
{
    (void)in_sizes; (void)n_in; (void)out_size;
    const float* x   = (const float*)d_in[0];
    const float* Wq  = (const float*)d_in[1];
    const float* bq  = (const float*)d_in[2];
    const float* Wk  = (const float*)d_in[3];
    const float* bk  = (const float*)d_in[4];
    const float* Wv  = (const float*)d_in[5];
    const float* bv  = (const float*)d_in[6];
    const float* Wo  = (const float*)d_in[7];
    const float* bo  = (const float*)d_in[8];
    const float* Er  = (const float*)d_in[9];
    const float* W1  = (const float*)d_in[10];
    const float* b1  = (const float*)d_in[11];
    const float* W2  = (const float*)d_in[12];
    const float* b2  = (const float*)d_in[13];
    const float* g1  = (const float*)d_in[14];
    const float* be1 = (const float*)d_in[15];
    const float* g2  = (const float*)d_in[16];
    const float* be2 = (const float*)d_in[17];
    float* y = (float*)d_out;

    float *px1, *prel, *px2, *px3;
    cudaGetSymbolAddress((void**)&px1,  g_x1);
    cudaGetSymbolAddress((void**)&prel, g_rel);
    cudaGetSymbolAddress((void**)&px2,  g_x2);
    cudaGetSymbolAddress((void**)&px3,  g_x3);

    __half *x1h,*x1l,*x3h,*x3l,*avh,*avl,*h1h,*h1l;
    __half *qf,*kf,*vf,*erf,*wq,*wk,*wv,*wo,*w1,*w2;
    cudaGetSymbolAddress((void**)&x1h, g_x1h); cudaGetSymbolAddress((void**)&x1l, g_x1l);
    cudaGetSymbolAddress((void**)&x3h, g_x3h); cudaGetSymbolAddress((void**)&x3l, g_x3l);
    cudaGetSymbolAddress((void**)&qf,  g_qf);
    cudaGetSymbolAddress((void**)&kf,  g_kf);
    cudaGetSymbolAddress((void**)&vf,  g_vf);
    cudaGetSymbolAddress((void**)&avh, g_avh); cudaGetSymbolAddress((void**)&avl, g_avl);
    cudaGetSymbolAddress((void**)&h1h, g_h1h); cudaGetSymbolAddress((void**)&h1l, g_h1l);
    cudaGetSymbolAddress((void**)&erf, g_erf);
    cudaGetSymbolAddress((void**)&wq, g_wq); cudaGetSymbolAddress((void**)&wk, g_wk);
    cudaGetSymbolAddress((void**)&wv, g_wv); cudaGetSymbolAddress((void**)&wo, g_wo);
    cudaGetSymbolAddress((void**)&w1, g_w1); cudaGetSymbolAddress((void**)&w2, g_w2);

    cudaFuncSetAttribute(gemm_mma<0,false,true>,  cudaFuncAttributeMaxDynamicSharedMemorySize, GEMM_SMEM);
    cudaFuncSetAttribute(gemm_mma<1,false,false>, cudaFuncAttributeMaxDynamicSharedMemorySize, GEMM_SMEM);
    cudaFuncSetAttribute(gemm_mma<1,true,false>,  cudaFuncAttributeMaxDynamicSharedMemorySize, GEMM_SMEM);
    cudaFuncSetAttribute(gemm_mma<2,false,false>, cudaFuncAttributeMaxDynamicSharedMemorySize, GEMM_SMEM);
    cudaFuncSetAttribute(rel_mma,   cudaFuncAttributeMaxDynamicSharedMemorySize, REL_SMEM);
    cudaFuncSetAttribute(flash_mma, cudaFuncAttributeMaxDynamicSharedMemorySize, FL_SMEM);

    // weight transpose + fp16 convert
    convBTf<<<dim3(DD/32, DD/32), 256>>>(Wq, wq, DD, DD);
    convBTf<<<dim3(DD/32, DD/32), 256>>>(Wk, wk, DD, DD);
    convBTf<<<dim3(DD/32, DD/32), 256>>>(Wv, wv, DD, DD);
    convBTf<<<dim3(DD/32, DD/32), 256>>>(Wo, wo, DD, DD);
    convBTf<<<dim3(FF/32, DD/32), 256>>>(W1, w1, DD, FF);
    convBTf<<<dim3(DD/32, FF/32), 256>>>(W2, w2, FF, DD);
    convEf<<<(SS*DH + 1023)/1024, 256>>>(Er, erf, SS*DH);

    // x1 = LN(x)
    ln_kernel<<<MM, 256>>>(x, g1, be1, px1, x1h, x1l);
    // q/k/v -> fp16 single
    gemm_mma<2,false,false><<<dim3(DD/128, MM/128), 256, GEMM_SMEM>>>(
        x1h, x1l, wq, bq, nullptr, nullptr, nullptr, nullptr, qf, DD, DD, 0.125f);
    gemm_mma<2,false,false><<<dim3(DD/128, MM/128), 256, GEMM_SMEM>>>(
        x1h, x1l, wk, bk, nullptr, nullptr, nullptr, nullptr, kf, DD, DD, 1.f);
    gemm_mma<2,false,false><<<dim3(DD/128, MM/128), 256, GEMM_SMEM>>>(
        x1h, x1l, wv, bv, nullptr, nullptr, nullptr, nullptr, vf, DD, DD, 1.f);
    // rel = q@Er^T (band tiles, fp16 single)
    rel_mma<<<dim3(SS/128, SS/128, BB*HH), 256, REL_SMEM>>>(qf, erf, prel);
    // fused attention (fp16 single-product)
    flash_mma<<<dim3(SS/64, BB*HH), 128, FL_SMEM>>>(qf, kf, vf, prel, avh, avl);
    // x2 = x1 + av@Wo + bo
    gemm_mma<0,false,true><<<dim3(DD/128, MM/128), 256, GEMM_SMEM>>>(
        avh, avl, wo, bo, px1, px2, nullptr, nullptr, nullptr, DD, DD, 1.f);
    // x3 = LN(x2)
    ln_kernel<<<MM, 256>>>(px2, g2, be2, px3, x3h, x3l);
    // h1 = relu(x3@W1+b1) -> fp16 hi/lo
    gemm_mma<1,true,false><<<dim3(FF/128, MM/128), 256, GEMM_SMEM>>>(
        x3h, x3l, w1, b1, nullptr, nullptr, h1h, h1l, nullptr, FF, DD, 1.f);
    // y = x3 + h1@W2 + b2
    gemm_mma<0,false,true><<<dim3(DD/128, MM/128), 256, GEMM_SMEM>>>(
        h1h, h1l, w2, b2, px3, y, nullptr, nullptr, nullptr, DD, FF, 1.f);
}

// round 10
// speedup vs baseline: 2.7935x; 1.7383x over previous
#include <cuda_runtime.h>
#include <cuda_fp16.h>
#include <math.h>
#include <stdint.h>

#define BB 2
#define SS 2048
#define DD 1024
#define HH 16
#define DH 64
#define FF 4096
#define MM (BB*SS)   // 4096 rows

// ---------------- scratch (device globals; no allocation allowed) ----------
__device__ float  g_x1 [MM*DD];
__device__ __half g_rel[(size_t)BB*HH*SS*SS];   // q@Er^T band, fp16 (268 MB)
__device__ float  g_x2 [MM*DD];
__device__ float  g_x3 [MM*DD];

__device__ __half g_x1f[MM*DD];
__device__ __half g_x3f[MM*DD];
__device__ __half g_qf [MM*DD];
__device__ __half g_kf [MM*DD];
__device__ __half g_vf [MM*DD];
__device__ __half g_avf[MM*DD];
__device__ __half g_h1f[(size_t)MM*FF];
__device__ __half g_erf[SS*DH];
__device__ __half g_wq[DD*DD], g_wk[DD*DD], g_wv[DD*DD], g_wo[DD*DD];
__device__ __half g_w1[(size_t)DD*FF], g_w2[(size_t)DD*FF];

// ======================= helpers ============================================
__device__ __forceinline__ uint32_t smem_u32(const void* p) {
    uint32_t a;
    asm("{ .reg .u64 t; cvta.to.shared.u64 t, %1; cvt.u32.u64 %0, t; }"
        : "=r"(a) : "l"(p));
    return a;
}
__device__ __forceinline__ void ldsm4(uint32_t* r, uint32_t addr) {
    asm volatile("ldmatrix.sync.aligned.m8n8.x4.shared.b16 {%0,%1,%2,%3}, [%4];"
        : "=r"(r[0]), "=r"(r[1]), "=r"(r[2]), "=r"(r[3]) : "r"(addr));
}
__device__ __forceinline__ void ldsm4t(uint32_t* r, uint32_t addr) {
    asm volatile("ldmatrix.sync.aligned.m8n8.x4.trans.shared.b16 {%0,%1,%2,%3}, [%4];"
        : "=r"(r[0]), "=r"(r[1]), "=r"(r[2]), "=r"(r[3]) : "r"(addr));
}
__device__ __forceinline__ void mma_f16(float* c, const uint32_t* a, const uint32_t* b) {
    asm volatile("mma.sync.aligned.m16n8k16.row.col.f32.f16.f16.f32 "
        "{%0,%1,%2,%3}, {%4,%5,%6,%7}, {%8,%9}, {%0,%1,%2,%3};"
        : "+f"(c[0]), "+f"(c[1]), "+f"(c[2]), "+f"(c[3])
        : "r"(a[0]), "r"(a[1]), "r"(a[2]), "r"(a[3]), "r"(b[0]), "r"(b[1]));
}
__device__ __forceinline__ uint32_t pack_f16(float x, float y) {
    __half2 h = __floats2half2_rn(x, y);
    return *(uint32_t*)&h;
}

#define RSTR 144
#define ASZ (128 * RSTR)          // 18432 B per 128x64 16-bit array
#define QSZ (64 * RSTR)           // 9216 B per 64x64 16-bit array

// ================== weight transpose + fp16: [K][N] -> [N][K] ===============
__global__ __launch_bounds__(256) void convBTf(
    const float* __restrict__ W, __half* __restrict__ T, int K, int N)
{
    __shared__ float ts[32][33];
    int n0 = blockIdx.x * 32, k0 = blockIdx.y * 32;
    int tx = threadIdx.x & 31, ty = threadIdx.x >> 5;
    #pragma unroll
    for (int i = 0; i < 4; i++)
        ts[ty + 8*i][tx] = W[(size_t)(k0 + ty + 8*i) * N + n0 + tx];
    __syncthreads();
    #pragma unroll
    for (int i = 0; i < 4; i++) {
        int n = ty + 8*i;
        T[(size_t)(n0 + n) * K + k0 + tx] = __float2half_rn(ts[tx][n]);
    }
}

// -------- elementwise f16 convert (Er) ---------------------------------------
__global__ __launch_bounds__(256) void convEf(
    const float* __restrict__ X, __half* __restrict__ Xf, int n)
{
    int i = blockIdx.x * 1024 + threadIdx.x * 4;
    if (i >= n) return;
    float4 v = *(const float4*)(X + i);
    *(__half2*)(Xf + i)     = __floats2half2_rn(v.x, v.y);
    *(__half2*)(Xf + i + 2) = __floats2half2_rn(v.z, v.w);
}

// ---------------- LayerNorm: fp32 out + fp16 out ----------------------------
__global__ __launch_bounds__(256) void ln_kernel(
    const float* __restrict__ X, const float* __restrict__ g,
    const float* __restrict__ be, float* __restrict__ Y,
    __half* __restrict__ Yf)
{
    int row = blockIdx.x;
    size_t base = (size_t)row * DD;
    int tid = threadIdx.x;
    float4 v = *(const float4*)(X + base + tid * 4);
    float s = v.x + v.y + v.z + v.w;
    float q = v.x*v.x + v.y*v.y + v.z*v.z + v.w*v.w;

    __shared__ float rs[32], rq[32];
    #pragma unroll
    for (int o = 16; o > 0; o >>= 1) {
        s += __shfl_xor_sync(0xFFFFFFFF, s, o);
        q += __shfl_xor_sync(0xFFFFFFFF, q, o);
    }
    int lane = tid & 31, w = tid >> 5;
    if (lane == 0) { rs[w] = s; rq[w] = q; }
    __syncthreads();
    if (w == 0) {
        s = (lane < 8) ? rs[lane] : 0.f;
        q = (lane < 8) ? rq[lane] : 0.f;
        #pragma unroll
        for (int o = 4; o > 0; o >>= 1) {
            s += __shfl_xor_sync(0xFFFFFFFF, s, o);
            q += __shfl_xor_sync(0xFFFFFFFF, q, o);
        }
        if (lane == 0) { rs[0] = s; rq[0] = q; }
    }
    __syncthreads();
    float mean = rs[0] * (1.f / DD);
    float var  = rq[0] * (1.f / DD) - mean * mean;
    float rstd = rsqrtf(var + 1e-5f);

    float4 gv = *(const float4*)(g  + tid * 4);
    float4 bv = *(const float4*)(be + tid * 4);
    float4 o4;
    o4.x = (v.x - mean) * rstd * gv.x + bv.x;
    o4.y = (v.y - mean) * rstd * gv.y + bv.y;
    o4.z = (v.z - mean) * rstd * gv.z + bv.z;
    o4.w = (v.w - mean) * rstd * gv.w + bv.w;
    *(float4*)(Y + base + tid * 4) = o4;
    *(__half2*)(Yf + base + tid*4)     = __floats2half2_rn(o4.x, o4.y);
    *(__half2*)(Yf + base + tid*4 + 2) = __floats2half2_rn(o4.z, o4.w);
}

// ====== mma.sync fp16 GEMM: C = epi(A@B^T + bias) ===========================
// A: [M][K] fp16 row-major.  B: [N][K] fp16 row-major.
// OUTM: 0 = f32, 2 = f16 single
#define SA 0
#define SB ASZ
#define GEMM_SMEM (2*ASZ)         // 36864 B

template<int OUTM, bool RELU, bool RES>
__global__ __launch_bounds__(256)
void gemm_mma(
    const __half* __restrict__ Am, const __half* __restrict__ Bm,
    const float* __restrict__ bias, const float* __restrict__ res,
    float* __restrict__ Cf, __half* __restrict__ Cs,
    int N, int K, float scale)
{
    extern __shared__ char smem[];
    uint32_t sb = smem_u32(smem);
    int tid = threadIdx.x;
    int lane = tid & 31, wid = tid >> 5;
    int wm = wid & 3, wn = wid >> 2;
    int m0 = blockIdx.y * 128, n0 = blockIdx.x * 128;

    int aRow = wm * 32 + ((lane >> 3) & 1) * 8 + (lane & 7);
    uint32_t aOff = (uint32_t)aRow * RSTR + ((lane >> 4) & 1) * 16;
    int bRow = wn * 64 + ((lane >> 4) & 1) * 8 + (lane & 7);
    uint32_t bOff = (uint32_t)bRow * RSTR + ((lane >> 3) & 1) * 16;

    float acc[2][8][4] = {};

    const int chunks = K >> 6;
    for (int c = 0; c < chunks; c++) {
        size_t koff = (size_t)c * 64;
        #pragma unroll
        for (int i = 0; i < 4; i++) {
            int u = tid + i * 256;
            int row = u >> 3, seg = u & 7;
            uint32_t d = (uint32_t)row * RSTR + seg * 16;
            *(uint4*)(smem + SA + d) = *((const uint4*)(Am + (size_t)(m0+row)*K + koff) + seg);
            *(uint4*)(smem + SB + d) = *((const uint4*)(Bm + (size_t)(n0+row)*K + koff) + seg);
        }
        __syncthreads();

        #pragma unroll
        for (int kk = 0; kk < 4; kk++) {
            uint32_t kb = kk * 32;
            uint32_t ah[2][4];
            ldsm4(ah[0], sb + SA + aOff + kb);
            ldsm4(ah[1], sb + SA + aOff + 16*RSTR + kb);
            uint32_t bh[4][4];
            #pragma unroll
            for (int jp = 0; jp < 4; jp++)
                ldsm4(bh[jp], sb + SB + bOff + (uint32_t)jp*16*RSTR + kb);
            #pragma unroll
            for (int im = 0; im < 2; im++)
                #pragma unroll
                for (int jn = 0; jn < 8; jn++)
                    mma_f16(acc[im][jn], ah[im], &bh[jn >> 1][(jn & 1) * 2]);
        }
        __syncthreads();
    }

    int r = lane >> 2, cc = (lane & 3) * 2;
    #pragma unroll
    for (int im = 0; im < 2; im++) {
        int rg0 = m0 + wm * 32 + im * 16 + r;
        #pragma unroll
        for (int jn = 0; jn < 8; jn++) {
            int col = n0 + wn * 64 + jn * 8 + cc;
            float2 bv = *(const float2*)(bias + col);
            float v0 = (acc[im][jn][0] + bv.x) * scale;
            float v1 = (acc[im][jn][1] + bv.y) * scale;
            float v2 = (acc[im][jn][2] + bv.x) * scale;
            float v3 = (acc[im][jn][3] + bv.y) * scale;
            if (RELU) {
                v0 = fmaxf(v0, 0.f); v1 = fmaxf(v1, 0.f);
                v2 = fmaxf(v2, 0.f); v3 = fmaxf(v3, 0.f);
            }
            size_t o0 = (size_t)rg0 * N + col;
            size_t o1 = (size_t)(rg0 + 8) * N + col;
            if (RES) {
                float2 r0 = *(const float2*)(res + o0);
                float2 r1 = *(const float2*)(res + o1);
                v0 += r0.x; v1 += r0.y; v2 += r1.x; v3 += r1.y;
            }
            if (OUTM == 0) {
                *(float2*)(Cf + o0) = make_float2(v0, v1);
                *(float2*)(Cf + o1) = make_float2(v2, v3);
            } else {
                *(__half2*)(Cs + o0) = __floats2half2_rn(v0, v1);
                *(__half2*)(Cs + o1) = __floats2half2_rn(v2, v3);
            }
        }
    }
}

// ========== rel = q @ Er^T, band tiles only, fp16 in/out (K = 64) ===========
#define REL_SMEM (2*ASZ)

__global__ __launch_bounds__(256)
void rel_mma(
    const __half* __restrict__ Qf, const __half* __restrict__ Ef,
    __half* __restrict__ out)
{
    int m0 = blockIdx.y * 128, n0 = blockIdx.x * 128;
    if (m0 + n0 + 255 < SS - 1) return;   // tile never read by skew gather
    int bh = blockIdx.z;
    int b = bh >> 4, h = bh & 15;

    extern __shared__ char smem[];
    uint32_t sb = smem_u32(smem);
    int tid = threadIdx.x;
    int lane = tid & 31, wid = tid >> 5;
    int wm = wid & 3, wn = wid >> 2;

    const __half* Qp = Qf + ((size_t)b * SS) * DD + h * DH;

    #pragma unroll
    for (int i = 0; i < 4; i++) {
        int u = tid + i * 256;
        int row = u >> 3, seg = u & 7;
        uint32_t d = (uint32_t)row * RSTR + seg * 16;
        *(uint4*)(smem + 0   + d) = *((const uint4*)(Qp + (size_t)(m0+row)*DD) + seg);
        *(uint4*)(smem + ASZ + d) = *((const uint4*)(Ef + (size_t)(n0+row)*DH) + seg);
    }
    __syncthreads();

    int aRow = wm * 32 + ((lane >> 3) & 1) * 8 + (lane & 7);
    uint32_t aOff = (uint32_t)aRow * RSTR + ((lane >> 4) & 1) * 16;
    int bRow = wn * 64 + ((lane >> 4) & 1) * 8 + (lane & 7);
    uint32_t bOff = (uint32_t)bRow * RSTR + ((lane >> 3) & 1) * 16;

    float acc[2][8][4] = {};
    #pragma unroll
    for (int kk = 0; kk < 4; kk++) {
        uint32_t kb = kk * 32;
        uint32_t ah[2][4];
        ldsm4(ah[0], sb + 0 + aOff + kb);
        ldsm4(ah[1], sb + 0 + aOff + 16*RSTR + kb);
        uint32_t bhf[4][4];
        #pragma unroll
        for (int jp = 0; jp < 4; jp++)
            ldsm4(bhf[jp], sb + ASZ + bOff + (uint32_t)jp*16*RSTR + kb);
        #pragma unroll
        for (int im = 0; im < 2; im++)
            #pragma unroll
            for (int jn = 0; jn < 8; jn++)
                mma_f16(acc[im][jn], ah[im], &bhf[jn >> 1][(jn & 1) * 2]);
    }

    __half* ob = out + (size_t)bh * SS * SS;
    int r = lane >> 2, cc = (lane & 3) * 2;
    #pragma unroll
    for (int im = 0; im < 2; im++) {
        int rg0 = m0 + wm * 32 + im * 16 + r;
        #pragma unroll
        for (int jn = 0; jn < 8; jn++) {
            int col = n0 + wn * 64 + jn * 8 + cc;
            *(__half2*)(ob + (size_t)rg0 * SS + col)     = __floats2half2_rn(acc[im][jn][0], acc[im][jn][1]);
            *(__half2*)(ob + (size_t)(rg0+8) * SS + col) = __floats2half2_rn(acc[im][jn][2], acc[im][jn][3]);
        }
    }
}

// ========== flash attention, fp16 single-product ============================
// CTA: one (b,h) and 64 q-rows, 128 threads (4 warps x 16 rows).
#define FL_Q  0
#define FL_K  QSZ
#define FL_V  (QSZ + ASZ)
#define FL_SMEM (QSZ + 2*ASZ)    // 46080 B

__global__ __launch_bounds__(128)
void flash_mma(
    const __half* __restrict__ Qf, const __half* __restrict__ Kf,
    const __half* __restrict__ Vf, const __half* __restrict__ REL,
    __half* __restrict__ Of)
{
    extern __shared__ char smem[];
    uint32_t sb = smem_u32(smem);
    int tid = threadIdx.x;
    int lane = tid & 31, w = tid >> 5;     // 4 warps
    int s0 = blockIdx.x * 64;
    int bh = blockIdx.y;
    int b = bh >> 4, h = bh & 15;

    const __half* qb = Qf + ((size_t)b * SS) * DD + h * DH;
    const __half* kb = Kf + ((size_t)b * SS) * DD + h * DH;
    const __half* vb = Vf + ((size_t)b * SS) * DD + h * DH;

    // stage Q (64 rows, persistent in smem)
    #pragma unroll
    for (int i = 0; i < 4; i++) {
        int u = tid + i * 128;
        int row = u >> 3, seg = u & 7;
        uint32_t d = (uint32_t)row * RSTR + seg * 16;
        *(uint4*)(smem + FL_Q + d) = *((const uint4*)(qb + (size_t)(s0+row)*DD) + seg);
    }

    int g = lane >> 2, qd = lane & 3;
    int sA = s0 + w * 16 + g;
    int sB = sA + 8;
    const __half* rpA = REL + ((size_t)bh * SS + sA) * SS + (SS - 1 - sA);
    const __half* rpB = REL + ((size_t)bh * SS + sB) * SS + (SS - 1 - sB);

    uint32_t aOff = (uint32_t)(w*16 + ((lane>>3)&1)*8 + (lane&7)) * RSTR + ((lane>>4)&1)*16;
    uint32_t bOff = (uint32_t)(((lane>>4)&1)*8 + (lane&7)) * RSTR + ((lane>>3)&1)*16;
    uint32_t vKr = ((lane>>3)&1)*8 + (lane&7);
    uint32_t vCb = ((lane>>4)&1)*16;

    float oacc[8][4] = {};
    float mA = -1e30f, mB = -1e30f, lA = 0.f, lB = 0.f;

    for (int c = 0; c < SS/128; c++) {
        int t0 = c * 128;
        __syncthreads();    // protect K/V smem reuse (and Q store on c==0)
        #pragma unroll
        for (int i = 0; i < 8; i++) {
            int u = tid + i * 128;
            int row = u >> 3, seg = u & 7;
            uint32_t d = (uint32_t)row * RSTR + seg * 16;
            *(uint4*)(smem + FL_K + d) = *((const uint4*)(kb + (size_t)(t0+row)*DD) + seg);
            *(uint4*)(smem + FL_V + d) = *((const uint4*)(vb + (size_t)(t0+row)*DD) + seg);
        }
        __syncthreads();

        // S = q @ k^T (fp16 single), 16 n-tiles of 8 cols
        float sacc[16][4] = {};
        #pragma unroll
        for (int kk = 0; kk < 4; kk++) {
            uint32_t kbo = kk * 32;
            uint32_t ah[4];
            ldsm4(ah, sb + FL_Q + aOff + kbo);
            #pragma unroll
            for (int jp = 0; jp < 8; jp++) {
                uint32_t bhf[4];
                ldsm4(bhf, sb + FL_K + bOff + (uint32_t)jp*16*RSTR + kbo);
                mma_f16(sacc[jp*2],   ah, &bhf[0]);
                mma_f16(sacc[jp*2+1], ah, &bhf[2]);
            }
        }

        // skew add (fp16 rel): sacc[jn][0,1] row sA, [2,3] row sB
        if (t0 <= sA) {
            #pragma unroll
            for (int jn = 0; jn < 16; jn++) {
                int t = t0 + jn * 8 + qd * 2;
                if (t     <= sA) sacc[jn][0] += __half2float(__ldg(rpA + t));
                if (t + 1 <= sA) sacc[jn][1] += __half2float(__ldg(rpA + t + 1));
            }
        }
        if (t0 <= sB) {
            #pragma unroll
            for (int jn = 0; jn < 16; jn++) {
                int t = t0 + jn * 8 + qd * 2;
                if (t     <= sB) sacc[jn][2] += __half2float(__ldg(rpB + t));
                if (t + 1 <= sB) sacc[jn][3] += __half2float(__ldg(rpB + t + 1));
            }
        }

        // online softmax
        float cmA = -1e30f, cmB = -1e30f;
        #pragma unroll
        for (int jn = 0; jn < 16; jn++) {
            cmA = fmaxf(cmA, fmaxf(sacc[jn][0], sacc[jn][1]));
            cmB = fmaxf(cmB, fmaxf(sacc[jn][2], sacc[jn][3]));
        }
        cmA = fmaxf(cmA, __shfl_xor_sync(0xFFFFFFFF, cmA, 1));
        cmA = fmaxf(cmA, __shfl_xor_sync(0xFFFFFFFF, cmA, 2));
        cmB = fmaxf(cmB, __shfl_xor_sync(0xFFFFFFFF, cmB, 1));
        cmB = fmaxf(cmB, __shfl_xor_sync(0xFFFFFFFF, cmB, 2));
        float mnA = fmaxf(mA, cmA), mnB = fmaxf(mB, cmB);
        float alA = __expf(mA - mnA), alB = __expf(mB - mnB);
        mA = mnA; mB = mnB;

        float suA = 0.f, suB = 0.f;
        #pragma unroll
        for (int jn = 0; jn < 16; jn++) {
            sacc[jn][0] = __expf(sacc[jn][0] - mnA);
            sacc[jn][1] = __expf(sacc[jn][1] - mnA);
            sacc[jn][2] = __expf(sacc[jn][2] - mnB);
            sacc[jn][3] = __expf(sacc[jn][3] - mnB);
            suA += sacc[jn][0] + sacc[jn][1];
            suB += sacc[jn][2] + sacc[jn][3];
        }
        suA += __shfl_xor_sync(0xFFFFFFFF, suA, 1);
        suA += __shfl_xor_sync(0xFFFFFFFF, suA, 2);
        suB += __shfl_xor_sync(0xFFFFFFFF, suB, 1);
        suB += __shfl_xor_sync(0xFFFFFFFF, suB, 2);
        lA = lA * alA + suA;
        lB = lB * alB + suB;

        // rescale O
        #pragma unroll
        for (int jn = 0; jn < 8; jn++) {
            oacc[jn][0] *= alA; oacc[jn][1] *= alA;
            oacc[jn][2] *= alB; oacc[jn][3] *= alB;
        }

        // O += P @ V (fp16 single), 8 k-steps of 16
        #pragma unroll
        for (int k2 = 0; k2 < 8; k2++) {
            uint32_t pa[4];
            pa[0] = pack_f16(sacc[2*k2][0],   sacc[2*k2][1]);
            pa[1] = pack_f16(sacc[2*k2][2],   sacc[2*k2][3]);
            pa[2] = pack_f16(sacc[2*k2+1][0], sacc[2*k2+1][1]);
            pa[3] = pack_f16(sacc[2*k2+1][2], sacc[2*k2+1][3]);
            uint32_t vRowOff = (uint32_t)(k2 * 16 + vKr) * RSTR;
            #pragma unroll
            for (int jp = 0; jp < 4; jp++) {
                uint32_t vh4[4];
                ldsm4t(vh4, sb + FL_V + vRowOff + vCb + jp * 32);
                mma_f16(oacc[jp*2],   pa, &vh4[0]);
                mma_f16(oacc[jp*2+1], pa, &vh4[2]);
            }
        }
    }

    // epilogue: normalize + fp16 store (for Wo GEMM)
    float invA = 1.f / lA, invB = 1.f / lB;
    #pragma unroll
    for (int jn = 0; jn < 8; jn++) {
        int col = h * DH + jn * 8 + qd * 2;
        size_t oA = ((size_t)b * SS + sA) * DD + col;
        size_t oB = ((size_t)b * SS + sB) * DD + col;
        *(__half2*)(Of + oA) = __floats2half2_rn(oacc[jn][0] * invA, oacc[jn][1] * invA);
        *(__half2*)(Of + oB) = __floats2half2_rn(oacc[jn][2] * invB, oacc[jn][3] * invB);
    }
}

// ---------------- launch ----------------------------------------------------
extern "C" void kernel_launch(void* const* d_in, const int* in_sizes, int n_in,
                              void* d_out, int out_size)
{
    (void)in_sizes; (void)n_in; (void)out_size;
    const float* x   = (const float*)d_in[0];
    const float* Wq  = (const float*)d_in[1];
    const float* bq  = (const float*)d_in[2];
    const float* Wk  = (const float*)d_in[3];
    const float* bk  = (const float*)d_in[4];
    const float* Wv  = (const float*)d_in[5];
    const float* bv  = (const float*)d_in[6];
    const float* Wo  = (const float*)d_in[7];
    const float* bo  = (const float*)d_in[8];
    const float* Er  = (const float*)d_in[9];
    const float* W1  = (const float*)d_in[10];
    const float* b1  = (const float*)d_in[11];
    const float* W2  = (const float*)d_in[12];
    const float* b2  = (const float*)d_in[13];
    const float* g1  = (const float*)d_in[14];
    const float* be1 = (const float*)d_in[15];
    const float* g2  = (const float*)d_in[16];
    const float* be2 = (const float*)d_in[17];
    float* y = (float*)d_out;

    float *px1, *px2, *px3;
    __half *prel;
    cudaGetSymbolAddress((void**)&px1,  g_x1);
    cudaGetSymbolAddress((void**)&prel, g_rel);
    cudaGetSymbolAddress((void**)&px2,  g_x2);
    cudaGetSymbolAddress((void**)&px3,  g_x3);

    __half *x1f,*x3f,*avf,*h1f;
    __half *qf,*kf,*vf,*erf,*wq,*wk,*wv,*wo,*w1,*w2;
    cudaGetSymbolAddress((void**)&x1f, g_x1f);
    cudaGetSymbolAddress((void**)&x3f, g_x3f);
    cudaGetSymbolAddress((void**)&qf,  g_qf);
    cudaGetSymbolAddress((void**)&kf,  g_kf);
    cudaGetSymbolAddress((void**)&vf,  g_vf);
    cudaGetSymbolAddress((void**)&avf, g_avf);
    cudaGetSymbolAddress((void**)&h1f, g_h1f);
    cudaGetSymbolAddress((void**)&erf, g_erf);
    cudaGetSymbolAddress((void**)&wq, g_wq); cudaGetSymbolAddress((void**)&wk, g_wk);
    cudaGetSymbolAddress((void**)&wv, g_wv); cudaGetSymbolAddress((void**)&wo, g_wo);
    cudaGetSymbolAddress((void**)&w1, g_w1); cudaGetSymbolAddress((void**)&w2, g_w2);

    cudaFuncSetAttribute(gemm_mma<0,false,true>,  cudaFuncAttributeMaxDynamicSharedMemorySize, GEMM_SMEM);
    cudaFuncSetAttribute(gemm_mma<2,false,false>, cudaFuncAttributeMaxDynamicSharedMemorySize, GEMM_SMEM);
    cudaFuncSetAttribute(gemm_mma<2,true,false>,  cudaFuncAttributeMaxDynamicSharedMemorySize, GEMM_SMEM);
    cudaFuncSetAttribute(rel_mma,   cudaFuncAttributeMaxDynamicSharedMemorySize, REL_SMEM);
    cudaFuncSetAttribute(flash_mma, cudaFuncAttributeMaxDynamicSharedMemorySize, FL_SMEM);

    // weight transpose + fp16 convert
    convBTf<<<dim3(DD/32, DD/32), 256>>>(Wq, wq, DD, DD);
    convBTf<<<dim3(DD/32, DD/32), 256>>>(Wk, wk, DD, DD);
    convBTf<<<dim3(DD/32, DD/32), 256>>>(Wv, wv, DD, DD);
    convBTf<<<dim3(DD/32, DD/32), 256>>>(Wo, wo, DD, DD);
    convBTf<<<dim3(FF/32, DD/32), 256>>>(W1, w1, DD, FF);
    convBTf<<<dim3(DD/32, FF/32), 256>>>(W2, w2, FF, DD);
    convEf<<<(SS*DH + 1023)/1024, 256>>>(Er, erf, SS*DH);

    // x1 = LN(x)
    ln_kernel<<<MM, 256>>>(x, g1, be1, px1, x1f);
    // q/k/v -> fp16 single
    gemm_mma<2,false,false><<<dim3(DD/128, MM/128), 256, GEMM_SMEM>>>(
        x1f, wq, bq, nullptr, nullptr, qf, DD, DD, 0.125f);
    gemm_mma<2,false,false><<<dim3(DD/128, MM/128), 256, GEMM_SMEM>>>(
        x1f, wk, bk, nullptr, nullptr, kf, DD, DD, 1.f);
    gemm_mma<2,false,false><<<dim3(DD/128, MM/128), 256, GEMM_SMEM>>>(
        x1f, wv, bv, nullptr, nullptr, vf, DD, DD, 1.f);
    // rel = q@Er^T (band tiles, fp16)
    rel_mma<<<dim3(SS/128, SS/128, BB*HH), 256, REL_SMEM>>>(qf, erf, prel);
    // fused attention
    flash_mma<<<dim3(SS/64, BB*HH), 128, FL_SMEM>>>(qf, kf, vf, prel, avf);
    // x2 = x1 + av@Wo + bo
    gemm_mma<0,false,true><<<dim3(DD/128, MM/128), 256, GEMM_SMEM>>>(
        avf, wo, bo, px1, px2, nullptr, DD, DD, 1.f);
    // x3 = LN(x2)
    ln_kernel<<<MM, 256>>>(px2, g2, be2, px3, x3f);
    // h1 = relu(x3@W1+b1) -> fp16
    gemm_mma<2,true,false><<<dim3(FF/128, MM/128), 256, GEMM_SMEM>>>(
        x3f, w1, b1, nullptr, nullptr, h1f, FF, DD, 1.f);
    // y = x3 + h1@W2 + b2
    gemm_mma<0,false,true><<<dim3(DD/128, MM/128), 256, GEMM_SMEM>>>(
        h1f, w2, b2, px3, y, nullptr, DD, FF, 1.f);
}